// round 1
// baseline (speedup 1.0000x reference)
#include <cuda_runtime.h>
#include <math.h>

#define NTOK 3072
#define DMODEL 256
#define NHEAD 8
#define DK 32
#define EPSV 1e-6f

// ---------------- scratch (device globals; no cudaMalloc allowed) ----------------
__device__ float g_Q[NTOK * DMODEL];
__device__ float g_K[NTOK * DMODEL];
__device__ float g_V[NTOK * DMODEL];
__device__ float g_A[NTOK * DMODEL];   // adj @ V_full
__device__ float g_X[NTOK * DMODEL];   // blended pre-output-proj
__device__ float g_rowsum[NTOK];

// ---------------- generic GEMM: C[M,Nc] = A[M,K] @ B[Nc,K]^T (+bias) ----------------
// BM=64, BN=64, BK=16, 256 threads, 4x4 per thread. All dims multiples of tiles.
__global__ void gemm_nt_kernel(const float* __restrict__ A, const float* __restrict__ B,
                               const float* __restrict__ bias, float* __restrict__ C,
                               int M, int Nc, int K)
{
    __shared__ float As[16][65];
    __shared__ float Bs[16][65];
    const int tid = threadIdx.x;
    const int tx = tid & 15, ty = tid >> 4;
    const int m0 = blockIdx.y * 64, n0 = blockIdx.x * 64;
    const int lr = tid >> 2;          // 0..63
    const int lc = (tid & 3) * 4;     // 0,4,8,12

    float acc[4][4] = {};

    for (int k0 = 0; k0 < K; k0 += 16) {
        float4 av = *(const float4*)(A + (size_t)(m0 + lr) * K + k0 + lc);
        float4 bv = *(const float4*)(B + (size_t)(n0 + lr) * K + k0 + lc);
        __syncthreads();
        As[lc + 0][lr] = av.x; As[lc + 1][lr] = av.y; As[lc + 2][lr] = av.z; As[lc + 3][lr] = av.w;
        Bs[lc + 0][lr] = bv.x; Bs[lc + 1][lr] = bv.y; Bs[lc + 2][lr] = bv.z; Bs[lc + 3][lr] = bv.w;
        __syncthreads();
        #pragma unroll
        for (int kk = 0; kk < 16; kk++) {
            float a[4], b[4];
            #pragma unroll
            for (int i = 0; i < 4; i++) a[i] = As[kk][ty * 4 + i];
            #pragma unroll
            for (int j = 0; j < 4; j++) b[j] = Bs[kk][tx * 4 + j];
            #pragma unroll
            for (int i = 0; i < 4; i++)
                #pragma unroll
                for (int j = 0; j < 4; j++)
                    acc[i][j] = fmaf(a[i], b[j], acc[i][j]);
        }
    }

    float bj[4] = {0.f, 0.f, 0.f, 0.f};
    if (bias) {
        #pragma unroll
        for (int j = 0; j < 4; j++) bj[j] = bias[n0 + tx * 4 + j];
    }
    #pragma unroll
    for (int i = 0; i < 4; i++) {
        #pragma unroll
        for (int j = 0; j < 4; j++)
            C[(size_t)(m0 + ty * 4 + i) * Nc + n0 + tx * 4 + j] = acc[i][j] + bj[j];
    }
}

// ---------------- C[M,Nc] = A[M,K] @ B[K,Nc] (no bias) ----------------
__global__ void gemm_nn_kernel(const float* __restrict__ A, const float* __restrict__ B,
                               float* __restrict__ C, int M, int Nc, int K)
{
    __shared__ float As[16][65];
    __shared__ float Bs[16][65];
    const int tid = threadIdx.x;
    const int tx = tid & 15, ty = tid >> 4;
    const int m0 = blockIdx.y * 64, n0 = blockIdx.x * 64;
    const int lr = tid >> 2;
    const int lc = (tid & 3) * 4;
    const int br = tid >> 4;          // 0..15
    const int bc = (tid & 15) * 4;    // 0..60

    float acc[4][4] = {};

    for (int k0 = 0; k0 < K; k0 += 16) {
        float4 av = *(const float4*)(A + (size_t)(m0 + lr) * K + k0 + lc);
        float4 bv = *(const float4*)(B + (size_t)(k0 + br) * Nc + n0 + bc);
        __syncthreads();
        As[lc + 0][lr] = av.x; As[lc + 1][lr] = av.y; As[lc + 2][lr] = av.z; As[lc + 3][lr] = av.w;
        Bs[br][bc + 0] = bv.x; Bs[br][bc + 1] = bv.y; Bs[br][bc + 2] = bv.z; Bs[br][bc + 3] = bv.w;
        __syncthreads();
        #pragma unroll
        for (int kk = 0; kk < 16; kk++) {
            float a[4], b[4];
            #pragma unroll
            for (int i = 0; i < 4; i++) a[i] = As[kk][ty * 4 + i];
            #pragma unroll
            for (int j = 0; j < 4; j++) b[j] = Bs[kk][tx * 4 + j];
            #pragma unroll
            for (int i = 0; i < 4; i++)
                #pragma unroll
                for (int j = 0; j < 4; j++)
                    acc[i][j] = fmaf(a[i], b[j], acc[i][j]);
        }
    }
    #pragma unroll
    for (int i = 0; i < 4; i++)
        #pragma unroll
        for (int j = 0; j < 4; j++)
            C[(size_t)(m0 + ty * 4 + i) * Nc + n0 + tx * 4 + j] = acc[i][j];
}

// ---------------- adjacency row sums ----------------
__global__ void rowsum_kernel(const float* __restrict__ adj, float* __restrict__ out)
{
    const int row = blockIdx.x;
    const float4* p = (const float4*)(adj + (size_t)row * NTOK);
    float s = 0.f;
    for (int i = threadIdx.x; i < NTOK / 4; i += 256) {
        float4 v = p[i];
        s += (v.x + v.y) + (v.z + v.w);
    }
    #pragma unroll
    for (int o = 16; o; o >>= 1) s += __shfl_xor_sync(0xffffffffu, s, o);
    __shared__ float red[8];
    if ((threadIdx.x & 31) == 0) red[threadIdx.x >> 5] = s;
    __syncthreads();
    if (threadIdx.x < 8) {
        s = red[threadIdx.x];
        #pragma unroll
        for (int o = 4; o; o >>= 1) s += __shfl_xor_sync(0xffu, s, o);
        if (threadIdx.x == 0) out[row] = s;
    }
}

// ---------------- flash attention + lambda blend epilogue ----------------
// grid: (NTOK/64, NHEAD); 256 threads. 64 q-rows per CTA, 64-key tiles, online softmax.
__global__ void flash_blend_kernel(const float* __restrict__ Q, const float* __restrict__ K,
                                   const float* __restrict__ V, const float* __restrict__ mask,
                                   const float* __restrict__ A, const float* __restrict__ rowsum,
                                   const float* __restrict__ lambdas, float* __restrict__ X)
{
    const int h  = blockIdx.y;
    const int q0 = blockIdx.x * 64;
    const int tid = threadIdx.x;

    __shared__ float Qs[64][33];
    __shared__ float Ks[64][33];
    __shared__ float Vs[64][36];
    __shared__ float Ps[64][65];
    __shared__ float m_sh[64], l_sh[64], alpha_sh[64];

    // load Q tile: 64 rows x 32 dims
    #pragma unroll
    for (int it = 0; it < 2; it++) {
        int i = tid + it * 256;           // 0..511 float4s
        int r = i >> 3, dg = (i & 7) * 4;
        float4 v = *(const float4*)(Q + (size_t)(q0 + r) * DMODEL + h * DK + dg);
        Qs[r][dg + 0] = v.x; Qs[r][dg + 1] = v.y; Qs[r][dg + 2] = v.z; Qs[r][dg + 3] = v.w;
    }
    if (tid < 64) { m_sh[tid] = -1e30f; l_sh[tid] = 0.f; }

    const int ty = tid >> 4, tx = tid & 15;
    const int r2 = (tid >> 3) * 2;       // PV rows: r2, r2+1
    const int c4 = (tid & 7) * 4;        // PV cols: c4..c4+3
    const int w = tid >> 5, lane = tid & 31;
    const float scale = 0.17677669529663687f;  // 1/sqrt(32)

    float o[2][4] = {};

    for (int kt = 0; kt < NTOK / 64; kt++) {
        const int k0 = kt * 64;
        __syncthreads();
        // load K/V tiles
        #pragma unroll
        for (int it = 0; it < 2; it++) {
            int i = tid + it * 256;
            int r = i >> 3, dg = (i & 7) * 4;
            float4 kv = *(const float4*)(K + (size_t)(k0 + r) * DMODEL + h * DK + dg);
            Ks[r][dg + 0] = kv.x; Ks[r][dg + 1] = kv.y; Ks[r][dg + 2] = kv.z; Ks[r][dg + 3] = kv.w;
            float4 vv = *(const float4*)(V + (size_t)(k0 + r) * DMODEL + h * DK + dg);
            Vs[r][dg + 0] = vv.x; Vs[r][dg + 1] = vv.y; Vs[r][dg + 2] = vv.z; Vs[r][dg + 3] = vv.w;
        }
        __syncthreads();

        // S = Qs @ Ks^T  (4x4 per thread)
        float s[4][4] = {};
        #pragma unroll
        for (int d = 0; d < 32; d++) {
            float a[4], b[4];
            #pragma unroll
            for (int i = 0; i < 4; i++) a[i] = Qs[ty * 4 + i][d];
            #pragma unroll
            for (int j = 0; j < 4; j++) b[j] = Ks[tx * 4 + j][d];
            #pragma unroll
            for (int i = 0; i < 4; i++)
                #pragma unroll
                for (int j = 0; j < 4; j++)
                    s[i][j] = fmaf(a[i], b[j], s[i][j]);
        }
        // scale + mask, stage into Ps
        #pragma unroll
        for (int i = 0; i < 4; i++) {
            int ry = ty * 4 + i;
            float4 mv = *(const float4*)(mask + (size_t)(q0 + ry) * NTOK + k0 + tx * 4);
            Ps[ry][tx * 4 + 0] = fmaf(s[i][0], scale, mv.x);
            Ps[ry][tx * 4 + 1] = fmaf(s[i][1], scale, mv.y);
            Ps[ry][tx * 4 + 2] = fmaf(s[i][2], scale, mv.z);
            Ps[ry][tx * 4 + 3] = fmaf(s[i][3], scale, mv.w);
        }
        __syncthreads();

        // online softmax: warp w handles rows w*8 .. w*8+7
        #pragma unroll
        for (int rr = 0; rr < 8; rr++) {
            int row = w * 8 + rr;
            float s0 = Ps[row][lane], s1 = Ps[row][lane + 32];
            float tm = fmaxf(s0, s1);
            #pragma unroll
            for (int off = 16; off; off >>= 1) tm = fmaxf(tm, __shfl_xor_sync(0xffffffffu, tm, off));
            float m_old = m_sh[row];
            float m_new = fmaxf(m_old, tm);
            float p0 = __expf(s0 - m_new), p1 = __expf(s1 - m_new);
            Ps[row][lane] = p0; Ps[row][lane + 32] = p1;
            float ps = p0 + p1;
            #pragma unroll
            for (int off = 16; off; off >>= 1) ps += __shfl_xor_sync(0xffffffffu, ps, off);
            if (lane == 0) {
                float al = __expf(m_old - m_new);
                l_sh[row] = l_sh[row] * al + ps;
                m_sh[row] = m_new;
                alpha_sh[row] = al;
            }
        }
        __syncthreads();

        // rescale + PV accumulate (2 rows x 4 cols per thread)
        float a0 = alpha_sh[r2], a1 = alpha_sh[r2 + 1];
        #pragma unroll
        for (int j = 0; j < 4; j++) { o[0][j] *= a0; o[1][j] *= a1; }
        #pragma unroll 8
        for (int k = 0; k < 64; k++) {
            float p0 = Ps[r2][k], p1 = Ps[r2 + 1][k];
            float4 v = *(const float4*)&Vs[k][c4];
            o[0][0] = fmaf(p0, v.x, o[0][0]); o[0][1] = fmaf(p0, v.y, o[0][1]);
            o[0][2] = fmaf(p0, v.z, o[0][2]); o[0][3] = fmaf(p0, v.w, o[0][3]);
            o[1][0] = fmaf(p1, v.x, o[1][0]); o[1][1] = fmaf(p1, v.y, o[1][1]);
            o[1][2] = fmaf(p1, v.z, o[1][2]); o[1][3] = fmaf(p1, v.w, o[1][3]);
        }
    }

    // epilogue: normalize + lambda blend with adjacency path
    const float lam0 = lambdas[0], lam1 = lambdas[1];
    #pragma unroll
    for (int i = 0; i < 2; i++) {
        int row = q0 + r2 + i;
        float invl = 1.f / l_sh[r2 + i];
        float inv_den = lam1 / (rowsum[row] + EPSV);
        #pragma unroll
        for (int j = 0; j < 4; j++) {
            int col = h * DK + c4 + j;
            X[(size_t)row * DMODEL + col] =
                lam0 * o[i][j] * invl + g_A[(size_t)row * DMODEL + col] * inv_den;
        }
    }
}

// ---------------- launch ----------------
extern "C" void kernel_launch(void* const* d_in, const int* in_sizes, int n_in,
                              void* d_out, int out_size)
{
    const float* query  = (const float*)d_in[0];
    const float* key    = (const float*)d_in[1];
    const float* value  = (const float*)d_in[2];
    const float* mask   = (const float*)d_in[3];
    const float* adj    = (const float*)d_in[4];
    const float* lambdas= (const float*)d_in[5];
    const float* Wq     = (const float*)d_in[6];
    const float* bq     = (const float*)d_in[7];
    const float* Wk     = (const float*)d_in[8];
    const float* bk     = (const float*)d_in[9];
    const float* Wv     = (const float*)d_in[10];
    const float* bv     = (const float*)d_in[11];
    const float* Wo     = (const float*)d_in[12];
    const float* bo     = (const float*)d_in[13];
    float* out = (float*)d_out;

    void *pQ, *pK, *pV, *pA, *pX, *pRS;
    cudaGetSymbolAddress(&pQ, g_Q);
    cudaGetSymbolAddress(&pK, g_K);
    cudaGetSymbolAddress(&pV, g_V);
    cudaGetSymbolAddress(&pA, g_A);
    cudaGetSymbolAddress(&pX, g_X);
    cudaGetSymbolAddress(&pRS, g_rowsum);

    dim3 gProj(DMODEL / 64, NTOK / 64);   // (4, 48)
    gemm_nt_kernel<<<gProj, 256>>>(query, Wq, bq, (float*)pQ, NTOK, DMODEL, DMODEL);
    gemm_nt_kernel<<<gProj, 256>>>(key,   Wk, bk, (float*)pK, NTOK, DMODEL, DMODEL);
    gemm_nt_kernel<<<gProj, 256>>>(value, Wv, bv, (float*)pV, NTOK, DMODEL, DMODEL);

    rowsum_kernel<<<NTOK, 256>>>(adj, (float*)pRS);

    gemm_nn_kernel<<<gProj, 256>>>(adj, (const float*)pV, (float*)pA, NTOK, DMODEL, NTOK);

    dim3 gFlash(NTOK / 64, NHEAD);        // (48, 8)
    flash_blend_kernel<<<gFlash, 256>>>((const float*)pQ, (const float*)pK, (const float*)pV,
                                        mask, (const float*)pA, (const float*)pRS,
                                        lambdas, (float*)pX);

    gemm_nt_kernel<<<gProj, 256>>>((const float*)pX, Wo, bo, out, NTOK, DMODEL, DMODEL);
}

// round 2
// speedup vs baseline: 1.3600x; 1.3600x over previous
#include <cuda_runtime.h>
#include <math.h>

#define NTOK 3072
#define DMODEL 256
#define NHEAD 8
#define DK 32
#define EPSV 1e-6f

// ---------------- scratch (device globals; no cudaMalloc allowed) ----------------
__device__ float g_Q[NTOK * DMODEL];
__device__ float g_K[NTOK * DMODEL];
__device__ float g_V[NTOK * DMODEL];
__device__ float g_A[NTOK * DMODEL];          // adj @ V_full (after reduce)
__device__ float g_X[NTOK * DMODEL];          // blended pre-output-proj
__device__ float g_rowsum[NTOK];
__device__ float g_part[4 * NTOK * DMODEL];   // split-K partials

// ---------------- projection GEMM: C[M,Nc] = A[M,K] @ B[Nc,K]^T (+bias) ----------------
// BM=64, BN=64, BK=16, 256 threads, 4x4 per thread (kept for small-K projections).
__global__ void gemm_nt_kernel(const float* __restrict__ A, const float* __restrict__ B,
                               const float* __restrict__ bias, float* __restrict__ C,
                               int M, int Nc, int K)
{
    __shared__ float As[16][65];
    __shared__ float Bs[16][65];
    const int tid = threadIdx.x;
    const int tx = tid & 15, ty = tid >> 4;
    const int m0 = blockIdx.y * 64, n0 = blockIdx.x * 64;
    const int lr = tid >> 2;          // 0..63
    const int lc = (tid & 3) * 4;     // 0,4,8,12

    float acc[4][4] = {};

    for (int k0 = 0; k0 < K; k0 += 16) {
        float4 av = *(const float4*)(A + (size_t)(m0 + lr) * K + k0 + lc);
        float4 bv = *(const float4*)(B + (size_t)(n0 + lr) * K + k0 + lc);
        __syncthreads();
        As[lc + 0][lr] = av.x; As[lc + 1][lr] = av.y; As[lc + 2][lr] = av.z; As[lc + 3][lr] = av.w;
        Bs[lc + 0][lr] = bv.x; Bs[lc + 1][lr] = bv.y; Bs[lc + 2][lr] = bv.z; Bs[lc + 3][lr] = bv.w;
        __syncthreads();
        #pragma unroll
        for (int kk = 0; kk < 16; kk++) {
            float a[4], b[4];
            #pragma unroll
            for (int i = 0; i < 4; i++) a[i] = As[kk][ty * 4 + i];
            #pragma unroll
            for (int j = 0; j < 4; j++) b[j] = Bs[kk][tx * 4 + j];
            #pragma unroll
            for (int i = 0; i < 4; i++)
                #pragma unroll
                for (int j = 0; j < 4; j++)
                    acc[i][j] = fmaf(a[i], b[j], acc[i][j]);
        }
    }

    float bj[4] = {0.f, 0.f, 0.f, 0.f};
    if (bias) {
        #pragma unroll
        for (int j = 0; j < 4; j++) bj[j] = bias[n0 + tx * 4 + j];
    }
    #pragma unroll
    for (int i = 0; i < 4; i++) {
        #pragma unroll
        for (int j = 0; j < 4; j++)
            C[(size_t)(m0 + ty * 4 + i) * Nc + n0 + tx * 4 + j] = acc[i][j] + bj[j];
    }
}

// ---------------- adj@V split-K GEMM: Cpart[kz] = adj[:, kz-chunk] @ V[kz-chunk, :] ----------------
// BM=128, BN=128, BK=16, split-K=4 (chunk 768). 256 threads, 8x8 per thread.
__global__ void gemm_adjv_splitk(const float* __restrict__ A, const float* __restrict__ B,
                                 float* __restrict__ Cpart)
{
    __shared__ float As[16][132];
    __shared__ float Bs[16][132];
    const int tid = threadIdx.x;
    const int tx = tid & 15, ty = tid >> 4;
    const int n0 = blockIdx.x * 128, m0 = blockIdx.y * 128;
    const int kz = blockIdx.z;
    const int kbeg = kz * 768;

    // A-load map: 128 rows x 16 cols, 2 float4/thread
    const int ar = tid >> 2;           // 0..63 (then +64)
    const int ac = (tid & 3) * 4;      // 0,4,8,12
    // B-load map: 16 rows x 128 cols, 2 float4/thread
    const int br = tid >> 5;           // 0..7 (then +8)
    const int bc = (tid & 31) * 4;     // 0..124

    float acc[8][8] = {};

    for (int k0 = kbeg; k0 < kbeg + 768; k0 += 16) {
        float4 av0 = *(const float4*)(A + (size_t)(m0 + ar) * NTOK + k0 + ac);
        float4 av1 = *(const float4*)(A + (size_t)(m0 + ar + 64) * NTOK + k0 + ac);
        float4 bv0 = *(const float4*)(B + (size_t)(k0 + br) * DMODEL + n0 + bc);
        float4 bv1 = *(const float4*)(B + (size_t)(k0 + br + 8) * DMODEL + n0 + bc);
        __syncthreads();
        As[ac + 0][ar] = av0.x; As[ac + 1][ar] = av0.y; As[ac + 2][ar] = av0.z; As[ac + 3][ar] = av0.w;
        As[ac + 0][ar + 64] = av1.x; As[ac + 1][ar + 64] = av1.y; As[ac + 2][ar + 64] = av1.z; As[ac + 3][ar + 64] = av1.w;
        *(float4*)&Bs[br][bc] = bv0;
        *(float4*)&Bs[br + 8][bc] = bv1;
        __syncthreads();
        #pragma unroll
        for (int kk = 0; kk < 16; kk++) {
            float4 a0 = *(const float4*)&As[kk][ty * 8];
            float4 a1 = *(const float4*)&As[kk][ty * 8 + 4];
            float4 b0 = *(const float4*)&Bs[kk][tx * 8];
            float4 b1 = *(const float4*)&Bs[kk][tx * 8 + 4];
            float a[8] = {a0.x, a0.y, a0.z, a0.w, a1.x, a1.y, a1.z, a1.w};
            float b[8] = {b0.x, b0.y, b0.z, b0.w, b1.x, b1.y, b1.z, b1.w};
            #pragma unroll
            for (int i = 0; i < 8; i++)
                #pragma unroll
                for (int j = 0; j < 8; j++)
                    acc[i][j] = fmaf(a[i], b[j], acc[i][j]);
        }
    }

    float* Cp = Cpart + (size_t)kz * (NTOK * DMODEL);
    #pragma unroll
    for (int i = 0; i < 8; i++) {
        int row = m0 + ty * 8 + i;
        *(float4*)&Cp[(size_t)row * DMODEL + n0 + tx * 8] =
            make_float4(acc[i][0], acc[i][1], acc[i][2], acc[i][3]);
        *(float4*)&Cp[(size_t)row * DMODEL + n0 + tx * 8 + 4] =
            make_float4(acc[i][4], acc[i][5], acc[i][6], acc[i][7]);
    }
}

// ---------------- split-K reduce: g_A = sum of 4 partials ----------------
__global__ void reduce4_kernel(const float* __restrict__ part, float* __restrict__ out)
{
    const int i = blockIdx.x * 256 + threadIdx.x;   // float4 index, total 196608
    const int Q = NTOK * DMODEL / 4;
    const float4* p = (const float4*)part;
    float4 a = p[i], b = p[i + Q], c = p[i + 2 * Q], d = p[i + 3 * Q];
    float4 r;
    r.x = (a.x + b.x) + (c.x + d.x);
    r.y = (a.y + b.y) + (c.y + d.y);
    r.z = (a.z + b.z) + (c.z + d.z);
    r.w = (a.w + b.w) + (c.w + d.w);
    ((float4*)out)[i] = r;
}

// ---------------- adjacency row sums ----------------
__global__ void rowsum_kernel(const float* __restrict__ adj, float* __restrict__ out)
{
    const int row = blockIdx.x;
    const float4* p = (const float4*)(adj + (size_t)row * NTOK);
    float s = 0.f;
    for (int i = threadIdx.x; i < NTOK / 4; i += 256) {
        float4 v = p[i];
        s += (v.x + v.y) + (v.z + v.w);
    }
    #pragma unroll
    for (int o = 16; o; o >>= 1) s += __shfl_xor_sync(0xffffffffu, s, o);
    __shared__ float red[8];
    if ((threadIdx.x & 31) == 0) red[threadIdx.x >> 5] = s;
    __syncthreads();
    if (threadIdx.x < 8) {
        s = red[threadIdx.x];
        #pragma unroll
        for (int o = 4; o; o >>= 1) s += __shfl_xor_sync(0xffu, s, o);
        if (threadIdx.x == 0) out[row] = s;
    }
}

// ---------------- flash attention (64 q x 128 k tiles) + lambda blend ----------------
// 256 threads. QK: 4x8 per thread. Softmax in registers via shfl over 16 col-lanes.
// PV: 2 rows x 4 dims per thread. Dynamic smem 78592 B -> 2 CTAs/SM.
__global__ void flash_blend2(const float* __restrict__ Q, const float* __restrict__ K,
                             const float* __restrict__ V, const float* __restrict__ mask,
                             const float* __restrict__ A, const float* __restrict__ rowsum,
                             const float* __restrict__ lambdas, float* __restrict__ X)
{
    extern __shared__ float sm[];
    float* Qs   = sm;                 // [32][68]  transposed
    float* Ks   = Qs + 32 * 68;       // [32][132] transposed
    float* Vs   = Ks + 32 * 132;      // [128][36]
    float* Ps   = Vs + 128 * 36;      // [64][132]
    float* m_sh = Ps + 64 * 132;      // [64]
    float* l_sh = m_sh + 64;          // [64]
    float* a_sh = l_sh + 64;          // [64]

    const int h  = blockIdx.y;
    const int q0 = blockIdx.x * 64;
    const int tid = threadIdx.x;
    const int ty = tid >> 4, tx = tid & 15, lane = tid & 31;
    const int rp = (tid >> 3) * 2;    // PV rows rp, rp+1
    const int cp = (tid & 7) * 4;     // PV dims
    const float scale = 0.17677669529663687f;   // 1/sqrt(32)

    // load Q tile (64 x 32) transposed
    #pragma unroll
    for (int it = 0; it < 2; it++) {
        int i = tid + it * 256;
        int r = i >> 3, c4 = (i & 7) * 4;
        float4 v = *(const float4*)(Q + (size_t)(q0 + r) * DMODEL + h * DK + c4);
        Qs[(c4 + 0) * 68 + r] = v.x; Qs[(c4 + 1) * 68 + r] = v.y;
        Qs[(c4 + 2) * 68 + r] = v.z; Qs[(c4 + 3) * 68 + r] = v.w;
    }
    if (tid < 64) { m_sh[tid] = -1e30f; l_sh[tid] = 0.f; }

    float o[2][4] = {};

    for (int kt = 0; kt < NTOK / 128; kt++) {
        const int k0 = kt * 128;
        __syncthreads();     // previous PV done reading Vs/Ps
        // load K (transposed) and V tiles: 128 rows x 32 dims
        #pragma unroll
        for (int it = 0; it < 4; it++) {
            int i = tid + it * 256;
            int r = i >> 3, c4 = (i & 7) * 4;
            float4 kv = *(const float4*)(K + (size_t)(k0 + r) * DMODEL + h * DK + c4);
            Ks[(c4 + 0) * 132 + r] = kv.x; Ks[(c4 + 1) * 132 + r] = kv.y;
            Ks[(c4 + 2) * 132 + r] = kv.z; Ks[(c4 + 3) * 132 + r] = kv.w;
            float4 vv = *(const float4*)(V + (size_t)(k0 + r) * DMODEL + h * DK + c4);
            *(float4*)&Vs[r * 36 + c4] = vv;
        }
        __syncthreads();

        // S = Q K^T : 4 rows x 8 cols per thread
        float s[4][8] = {};
        #pragma unroll
        for (int d = 0; d < 32; d++) {
            float4 aq = *(const float4*)&Qs[d * 68 + ty * 4];       // half-warp broadcast
            float4 b0 = *(const float4*)&Ks[d * 132 + tx * 8];
            float4 b1 = *(const float4*)&Ks[d * 132 + tx * 8 + 4];
            float av[4] = {aq.x, aq.y, aq.z, aq.w};
            float bv[8] = {b0.x, b0.y, b0.z, b0.w, b1.x, b1.y, b1.z, b1.w};
            #pragma unroll
            for (int i = 0; i < 4; i++)
                #pragma unroll
                for (int j = 0; j < 8; j++)
                    s[i][j] = fmaf(av[i], bv[j], s[i][j]);
        }

        // scale + mask + online softmax (row = 16 col-lanes of a half-warp)
        #pragma unroll
        for (int i = 0; i < 4; i++) {
            const int row = ty * 4 + i;
            const float* mrow = mask + (size_t)(q0 + row) * NTOK + k0 + tx * 8;
            float4 m0 = *(const float4*)mrow;
            float4 m1 = *(const float4*)(mrow + 4);
            float t[8];
            t[0] = fmaf(s[i][0], scale, m0.x); t[1] = fmaf(s[i][1], scale, m0.y);
            t[2] = fmaf(s[i][2], scale, m0.z); t[3] = fmaf(s[i][3], scale, m0.w);
            t[4] = fmaf(s[i][4], scale, m1.x); t[5] = fmaf(s[i][5], scale, m1.y);
            t[6] = fmaf(s[i][6], scale, m1.z); t[7] = fmaf(s[i][7], scale, m1.w);
            float mx = t[0];
            #pragma unroll
            for (int j = 1; j < 8; j++) mx = fmaxf(mx, t[j]);
            #pragma unroll
            for (int off = 1; off < 16; off <<= 1)
                mx = fmaxf(mx, __shfl_xor_sync(0xffffffffu, mx, off));
            const float mo = m_sh[row];
            const float mn = fmaxf(mo, mx);
            float p[8], ps = 0.f;
            #pragma unroll
            for (int j = 0; j < 8; j++) { p[j] = __expf(t[j] - mn); ps += p[j]; }
            #pragma unroll
            for (int off = 1; off < 16; off <<= 1)
                ps += __shfl_xor_sync(0xffffffffu, ps, off);
            if ((lane & 15) == 0) {
                float al = __expf(mo - mn);
                l_sh[row] = l_sh[row] * al + ps;
                m_sh[row] = mn;
                a_sh[row] = al;
            }
            *(float4*)&Ps[row * 132 + tx * 8]     = make_float4(p[0], p[1], p[2], p[3]);
            *(float4*)&Ps[row * 132 + tx * 8 + 4] = make_float4(p[4], p[5], p[6], p[7]);
        }
        __syncthreads();

        // PV accumulate: 2 rows x 4 dims per thread
        const float a0 = a_sh[rp], a1 = a_sh[rp + 1];
        #pragma unroll
        for (int j = 0; j < 4; j++) { o[0][j] *= a0; o[1][j] *= a1; }
        const float* p0r = &Ps[rp * 132];
        const float* p1r = p0r + 132;
        #pragma unroll 4
        for (int k = 0; k < 128; k++) {
            float p0 = p0r[k], p1 = p1r[k];
            float4 v = *(const float4*)&Vs[k * 36 + cp];
            o[0][0] = fmaf(p0, v.x, o[0][0]); o[0][1] = fmaf(p0, v.y, o[0][1]);
            o[0][2] = fmaf(p0, v.z, o[0][2]); o[0][3] = fmaf(p0, v.w, o[0][3]);
            o[1][0] = fmaf(p1, v.x, o[1][0]); o[1][1] = fmaf(p1, v.y, o[1][1]);
            o[1][2] = fmaf(p1, v.z, o[1][2]); o[1][3] = fmaf(p1, v.w, o[1][3]);
        }
    }
    __syncthreads();   // l_sh final values visible to PV-mapped threads

    // epilogue: normalize + lambda blend with adjacency path
    const float lam0 = lambdas[0], lam1 = lambdas[1];
    #pragma unroll
    for (int i = 0; i < 2; i++) {
        const int row = q0 + rp + i;
        const float invl = lam0 / l_sh[rp + i];
        const float invd = lam1 / (rowsum[row] + EPSV);
        #pragma unroll
        for (int j = 0; j < 4; j++) {
            const int col = h * DK + cp + j;
            X[(size_t)row * DMODEL + col] = o[i][j] * invl + A[(size_t)row * DMODEL + col] * invd;
        }
    }
}

// ---------------- launch ----------------
extern "C" void kernel_launch(void* const* d_in, const int* in_sizes, int n_in,
                              void* d_out, int out_size)
{
    const float* query  = (const float*)d_in[0];
    const float* key    = (const float*)d_in[1];
    const float* value  = (const float*)d_in[2];
    const float* mask   = (const float*)d_in[3];
    const float* adj    = (const float*)d_in[4];
    const float* lambdas= (const float*)d_in[5];
    const float* Wq     = (const float*)d_in[6];
    const float* bq     = (const float*)d_in[7];
    const float* Wk     = (const float*)d_in[8];
    const float* bk     = (const float*)d_in[9];
    const float* Wv     = (const float*)d_in[10];
    const float* bv     = (const float*)d_in[11];
    const float* Wo     = (const float*)d_in[12];
    const float* bo     = (const float*)d_in[13];
    float* out = (float*)d_out;

    void *pQ, *pK, *pV, *pA, *pX, *pRS, *pPart;
    cudaGetSymbolAddress(&pQ, g_Q);
    cudaGetSymbolAddress(&pK, g_K);
    cudaGetSymbolAddress(&pV, g_V);
    cudaGetSymbolAddress(&pA, g_A);
    cudaGetSymbolAddress(&pX, g_X);
    cudaGetSymbolAddress(&pRS, g_rowsum);
    cudaGetSymbolAddress(&pPart, g_part);

    const int flash_smem = (32 * 68 + 32 * 132 + 128 * 36 + 64 * 132 + 192) * 4;  // 78592 B
    cudaFuncSetAttribute(flash_blend2, cudaFuncAttributeMaxDynamicSharedMemorySize, flash_smem);

    dim3 gProj(DMODEL / 64, NTOK / 64);   // (4, 48)
    gemm_nt_kernel<<<gProj, 256>>>(query, Wq, bq, (float*)pQ, NTOK, DMODEL, DMODEL);
    gemm_nt_kernel<<<gProj, 256>>>(key,   Wk, bk, (float*)pK, NTOK, DMODEL, DMODEL);
    gemm_nt_kernel<<<gProj, 256>>>(value, Wv, bv, (float*)pV, NTOK, DMODEL, DMODEL);

    rowsum_kernel<<<NTOK, 256>>>(adj, (float*)pRS);

    dim3 gAdjV(DMODEL / 128, NTOK / 128, 4);  // (2, 24, 4)
    gemm_adjv_splitk<<<gAdjV, 256>>>(adj, (const float*)pV, (float*)pPart);
    reduce4_kernel<<<NTOK * DMODEL / 4 / 256, 256>>>((const float*)pPart, (float*)pA);

    dim3 gFlash(NTOK / 64, NHEAD);        // (48, 8)
    flash_blend2<<<gFlash, 256, flash_smem>>>((const float*)pQ, (const float*)pK, (const float*)pV,
                                              mask, (const float*)pA, (const float*)pRS,
                                              lambdas, (float*)pX);

    gemm_nt_kernel<<<gProj, 256>>>((const float*)pX, Wo, bo, out, NTOK, DMODEL, DMODEL);
}

// round 6
// speedup vs baseline: 1.3861x; 1.0191x over previous
#include <cuda_runtime.h>
#include <math.h>
#include <stdint.h>

#define NTOK 3072
#define DMODEL 256
#define NHEAD 8
#define DK 32
#define EPSV 1e-6f

// ---------------- scratch ----------------
__device__ float g_Q[NTOK * DMODEL];
__device__ float g_K[NTOK * DMODEL];
__device__ float g_V[NTOK * DMODEL];
__device__ float g_Vt[DMODEL * NTOK];         // V transposed [256][3072]
__device__ float g_A[NTOK * DMODEL];          // adj @ V (after reduce)
__device__ float g_X[NTOK * DMODEL];
__device__ float g_rowsum[NTOK];
__device__ float g_part[4 * NTOK * DMODEL];   // split-K partials

// ================= tf32x3 mma.sync GEMM =================
// C[M,256] = A[M,K] @ B[256,K]^T (+bias), K-major rows. fp32 accuracy via
// hi/lo tf32 split: acc += hi*hi + hi*lo + lo*hi  (lo*lo ~2^-22, dropped).
// BM=128, BN=128, BK=16. 8 warps 2(m)x4(n); warp tile 64x32 via m16n8k8.
__device__ __forceinline__ void mma_tf32(float* c, const uint32_t* a, const uint32_t* b)
{
    asm volatile(
        "mma.sync.aligned.m16n8k8.row.col.f32.tf32.tf32.f32 "
        "{%0,%1,%2,%3}, {%4,%5,%6,%7}, {%8,%9}, {%0,%1,%2,%3};"
        : "+f"(c[0]), "+f"(c[1]), "+f"(c[2]), "+f"(c[3])
        : "r"(a[0]), "r"(a[1]), "r"(a[2]), "r"(a[3]), "r"(b[0]), "r"(b[1]));
}

__device__ __forceinline__ float tf32_rna(float x)
{
    float y;
    asm("cvt.rna.tf32.f32 %0, %1;" : "=f"(y) : "f"(x));
    return y;
}

__global__ void __launch_bounds__(256) gemm_mma(const float* __restrict__ A, int lda,
                                                const float* __restrict__ B, int ldb,
                                                const float* __restrict__ bias,
                                                float* __restrict__ C,
                                                int kchunk, int part_stride)
{
    __shared__ float Ah[16][132];
    __shared__ float Al[16][132];
    __shared__ float Bh[16][132];
    __shared__ float Bl[16][132];
    const int tid = threadIdx.x;
    const int lane = tid & 31, wid = tid >> 5;
    const int wm = wid >> 2;          // 0..1 -> m offset 64
    const int wn = wid & 3;           // 0..3 -> n offset 32
    const int n0 = blockIdx.x * 128;
    const int m0 = blockIdx.y * 128;
    const int kbeg = blockIdx.z * kchunk;

    const int lr = tid >> 1;              // 0..127
    const int lc = (tid & 1) * 8;         // 0 or 8

    float acc[4][4][4] = {};

    for (int k0 = 0; k0 < kchunk; k0 += 16) {
        float av[8], bv[8];
        *(float4*)&av[0] = *(const float4*)(A + (size_t)(m0 + lr) * lda + kbeg + k0 + lc);
        *(float4*)&av[4] = *(const float4*)(A + (size_t)(m0 + lr) * lda + kbeg + k0 + lc + 4);
        *(float4*)&bv[0] = *(const float4*)(B + (size_t)(n0 + lr) * ldb + kbeg + k0 + lc);
        *(float4*)&bv[4] = *(const float4*)(B + (size_t)(n0 + lr) * ldb + kbeg + k0 + lc + 4);
        __syncthreads();
        #pragma unroll
        for (int j = 0; j < 8; j++) {
            float ah = tf32_rna(av[j]);
            float bh = tf32_rna(bv[j]);
            Ah[lc + j][lr] = ah; Al[lc + j][lr] = av[j] - ah;
            Bh[lc + j][lr] = bh; Bl[lc + j][lr] = bv[j] - bh;
        }
        __syncthreads();

        #pragma unroll
        for (int ks = 0; ks < 2; ks++) {
            const int kk = ks * 8 + (lane & 3);
            const int mrow = wm * 64 + (lane >> 2);
            const int ncol = wn * 32 + (lane >> 2);
            uint32_t ah[4][4], al[4][4], bh[4][2], bl[4][2];
            #pragma unroll
            for (int mt = 0; mt < 4; mt++) {
                ah[mt][0] = __float_as_uint(Ah[kk][mrow + mt * 16]);
                ah[mt][1] = __float_as_uint(Ah[kk][mrow + mt * 16 + 8]);
                ah[mt][2] = __float_as_uint(Ah[kk + 4][mrow + mt * 16]);
                ah[mt][3] = __float_as_uint(Ah[kk + 4][mrow + mt * 16 + 8]);
                al[mt][0] = __float_as_uint(Al[kk][mrow + mt * 16]);
                al[mt][1] = __float_as_uint(Al[kk][mrow + mt * 16 + 8]);
                al[mt][2] = __float_as_uint(Al[kk + 4][mrow + mt * 16]);
                al[mt][3] = __float_as_uint(Al[kk + 4][mrow + mt * 16 + 8]);
            }
            #pragma unroll
            for (int nt = 0; nt < 4; nt++) {
                bh[nt][0] = __float_as_uint(Bh[kk][ncol + nt * 8]);
                bh[nt][1] = __float_as_uint(Bh[kk + 4][ncol + nt * 8]);
                bl[nt][0] = __float_as_uint(Bl[kk][ncol + nt * 8]);
                bl[nt][1] = __float_as_uint(Bl[kk + 4][ncol + nt * 8]);
            }
            #pragma unroll
            for (int mt = 0; mt < 4; mt++)
                #pragma unroll
                for (int nt = 0; nt < 4; nt++) {
                    mma_tf32(acc[mt][nt], ah[mt], bl[nt]);
                    mma_tf32(acc[mt][nt], al[mt], bh[nt]);
                    mma_tf32(acc[mt][nt], ah[mt], bh[nt]);
                }
        }
    }

    // epilogue
    float* Cp = C + (size_t)blockIdx.z * part_stride;
    const int r0 = m0 + wm * 64 + (lane >> 2);
    const int c0 = n0 + wn * 32 + (lane & 3) * 2;
    #pragma unroll
    for (int nt = 0; nt < 4; nt++) {
        const int col = c0 + nt * 8;
        float2 bb = bias ? *(const float2*)(bias + col) : make_float2(0.f, 0.f);
        #pragma unroll
        for (int mt = 0; mt < 4; mt++) {
            const int row = r0 + mt * 16;
            *(float2*)(Cp + (size_t)row * DMODEL + col) =
                make_float2(acc[mt][nt][0] + bb.x, acc[mt][nt][1] + bb.y);
            *(float2*)(Cp + (size_t)(row + 8) * DMODEL + col) =
                make_float2(acc[mt][nt][2] + bb.x, acc[mt][nt][3] + bb.y);
        }
    }
}

// ================= transpose V -> Vt =================
__global__ void transpose_v(const float* __restrict__ src, float* __restrict__ dst)
{
    __shared__ float t[32][33];
    const int x0 = blockIdx.x * 32;   // token
    const int y0 = blockIdx.y * 32;   // dim
    #pragma unroll
    for (int j = 0; j < 32; j += 8)
        t[threadIdx.y + j][threadIdx.x] =
            src[(size_t)(x0 + threadIdx.y + j) * DMODEL + y0 + threadIdx.x];
    __syncthreads();
    #pragma unroll
    for (int j = 0; j < 32; j += 8)
        dst[(size_t)(y0 + threadIdx.y + j) * NTOK + x0 + threadIdx.x] =
            t[threadIdx.x][threadIdx.y + j];
}

// ================= split-K reduce (4 parts) =================
__global__ void reduce4_kernel(const float* __restrict__ part, float* __restrict__ out)
{
    const int i = blockIdx.x * 256 + threadIdx.x;
    const int Q = NTOK * DMODEL / 4;
    const float4* p = (const float4*)part;
    float4 a = p[i], b = p[i + Q], c = p[i + 2 * Q], d = p[i + 3 * Q];
    float4 r;
    r.x = (a.x + b.x) + (c.x + d.x);
    r.y = (a.y + b.y) + (c.y + d.y);
    r.z = (a.z + b.z) + (c.z + d.z);
    r.w = (a.w + b.w) + (c.w + d.w);
    ((float4*)out)[i] = r;
}

// ================= adjacency row sums =================
__global__ void rowsum_kernel(const float* __restrict__ adj, float* __restrict__ out)
{
    const int row = blockIdx.x;
    const float4* p = (const float4*)(adj + (size_t)row * NTOK);
    float s = 0.f;
    for (int i = threadIdx.x; i < NTOK / 4; i += 256) {
        float4 v = p[i];
        s += (v.x + v.y) + (v.z + v.w);
    }
    #pragma unroll
    for (int o = 16; o; o >>= 1) s += __shfl_xor_sync(0xffffffffu, s, o);
    __shared__ float red[8];
    if ((threadIdx.x & 31) == 0) red[threadIdx.x >> 5] = s;
    __syncthreads();
    if (threadIdx.x < 8) {
        s = red[threadIdx.x];
        #pragma unroll
        for (int o = 4; o; o >>= 1) s += __shfl_xor_sync(0xffu, s, o);
        if (threadIdx.x == 0) out[row] = s;
    }
}

// ================= flash attention + lambda blend =================
// 64 q-rows x 128-key tiles, 256 threads, 3 CTAs/SM (75776 B smem).
#define M_SH(r) Ps[(r) * 132 + 128]
#define L_SH(r) Ps[(r) * 132 + 129]
#define A_SH(r) Ps[(r) * 132 + 130]

__global__ void __launch_bounds__(256, 3)
flash_blend2(const float* __restrict__ Q, const float* __restrict__ K,
             const float* __restrict__ V, const float* __restrict__ mask,
             const float* __restrict__ A, const float* __restrict__ rowsum,
             const float* __restrict__ lambdas, float* __restrict__ X)
{
    extern __shared__ float smf[];
    float* Qs = smf;                  // [32][68]  (transposed)
    float* Ks = Qs + 32 * 68;         // [32][132] (transposed)
    float* Vs = Ks + 32 * 132;        // [128][32]
    float* Ps = Vs + 128 * 32;        // [64][132] (cols 128-130 = m/l/alpha)

    const int h  = blockIdx.y;
    const int q0 = blockIdx.x * 64;
    const int tid = threadIdx.x;
    const int ty = tid >> 4, tx = tid & 15, lane = tid & 31;
    const int rp = (tid >> 3) * 2;
    const int cp = (tid & 7) * 4;
    const float scale = 0.17677669529663687f;

    #pragma unroll
    for (int it = 0; it < 2; it++) {
        int i = tid + it * 256;
        int r = i >> 3, c4 = (i & 7) * 4;
        float4 v = *(const float4*)(Q + (size_t)(q0 + r) * DMODEL + h * DK + c4);
        Qs[(c4 + 0) * 68 + r] = v.x; Qs[(c4 + 1) * 68 + r] = v.y;
        Qs[(c4 + 2) * 68 + r] = v.z; Qs[(c4 + 3) * 68 + r] = v.w;
    }
    if (tid < 64) { M_SH(tid) = -1e30f; L_SH(tid) = 0.f; }

    float o[2][4] = {};

    for (int kt = 0; kt < NTOK / 128; kt++) {
        const int k0 = kt * 128;
        __syncthreads();
        #pragma unroll
        for (int it = 0; it < 4; it++) {
            int i = tid + it * 256;
            int r = i >> 3, c4 = (i & 7) * 4;
            float4 kv = *(const float4*)(K + (size_t)(k0 + r) * DMODEL + h * DK + c4);
            Ks[(c4 + 0) * 132 + r] = kv.x; Ks[(c4 + 1) * 132 + r] = kv.y;
            Ks[(c4 + 2) * 132 + r] = kv.z; Ks[(c4 + 3) * 132 + r] = kv.w;
            float4 vv = *(const float4*)(V + (size_t)(k0 + r) * DMODEL + h * DK + c4);
            *(float4*)&Vs[r * 32 + c4] = vv;
        }
        __syncthreads();

        float s[4][8] = {};
        #pragma unroll
        for (int d = 0; d < 32; d++) {
            float4 aq = *(const float4*)&Qs[d * 68 + ty * 4];
            float4 b0 = *(const float4*)&Ks[d * 132 + tx * 8];
            float4 b1 = *(const float4*)&Ks[d * 132 + tx * 8 + 4];
            float av[4] = {aq.x, aq.y, aq.z, aq.w};
            float bv[8] = {b0.x, b0.y, b0.z, b0.w, b1.x, b1.y, b1.z, b1.w};
            #pragma unroll
            for (int i = 0; i < 4; i++)
                #pragma unroll
                for (int j = 0; j < 8; j++)
                    s[i][j] = fmaf(av[i], bv[j], s[i][j]);
        }

        #pragma unroll
        for (int i = 0; i < 4; i++) {
            const int row = ty * 4 + i;
            const float* mrow = mask + (size_t)(q0 + row) * NTOK + k0 + tx * 8;
            float4 m0 = *(const float4*)mrow;
            float4 m1 = *(const float4*)(mrow + 4);
            float t[8];
            t[0] = fmaf(s[i][0], scale, m0.x); t[1] = fmaf(s[i][1], scale, m0.y);
            t[2] = fmaf(s[i][2], scale, m0.z); t[3] = fmaf(s[i][3], scale, m0.w);
            t[4] = fmaf(s[i][4], scale, m1.x); t[5] = fmaf(s[i][5], scale, m1.y);
            t[6] = fmaf(s[i][6], scale, m1.z); t[7] = fmaf(s[i][7], scale, m1.w);
            float mx = t[0];
            #pragma unroll
            for (int j = 1; j < 8; j++) mx = fmaxf(mx, t[j]);
            #pragma unroll
            for (int off = 1; off < 16; off <<= 1)
                mx = fmaxf(mx, __shfl_xor_sync(0xffffffffu, mx, off));
            const float mo = M_SH(row);
            const float mn = fmaxf(mo, mx);
            float p[8], ps = 0.f;
            #pragma unroll
            for (int j = 0; j < 8; j++) { p[j] = __expf(t[j] - mn); ps += p[j]; }
            #pragma unroll
            for (int off = 1; off < 16; off <<= 1)
                ps += __shfl_xor_sync(0xffffffffu, ps, off);
            if ((lane & 15) == 0) {
                float al = __expf(mo - mn);
                L_SH(row) = L_SH(row) * al + ps;
                M_SH(row) = mn;
                A_SH(row) = al;
            }
            *(float4*)&Ps[row * 132 + tx * 8]     = make_float4(p[0], p[1], p[2], p[3]);
            *(float4*)&Ps[row * 132 + tx * 8 + 4] = make_float4(p[4], p[5], p[6], p[7]);
        }
        __syncthreads();

        const float a0 = A_SH(rp), a1 = A_SH(rp + 1);
        #pragma unroll
        for (int j = 0; j < 4; j++) { o[0][j] *= a0; o[1][j] *= a1; }
        const float* p0r = &Ps[rp * 132];
        const float* p1r = p0r + 132;
        #pragma unroll 4
        for (int k = 0; k < 128; k++) {
            float p0 = p0r[k], p1 = p1r[k];
            float4 v = *(const float4*)&Vs[k * 32 + cp];
            o[0][0] = fmaf(p0, v.x, o[0][0]); o[0][1] = fmaf(p0, v.y, o[0][1]);
            o[0][2] = fmaf(p0, v.z, o[0][2]); o[0][3] = fmaf(p0, v.w, o[0][3]);
            o[1][0] = fmaf(p1, v.x, o[1][0]); o[1][1] = fmaf(p1, v.y, o[1][1]);
            o[1][2] = fmaf(p1, v.z, o[1][2]); o[1][3] = fmaf(p1, v.w, o[1][3]);
        }
    }
    __syncthreads();

    const float lam0 = lambdas[0], lam1 = lambdas[1];
    #pragma unroll
    for (int i = 0; i < 2; i++) {
        const int row = q0 + rp + i;
        const float invl = lam0 / L_SH(rp + i);
        const float invd = lam1 / (rowsum[row] + EPSV);
        #pragma unroll
        for (int j = 0; j < 4; j++) {
            const int col = h * DK + cp + j;
            X[(size_t)row * DMODEL + col] = o[i][j] * invl + A[(size_t)row * DMODEL + col] * invd;
        }
    }
}

// ================= launch =================
extern "C" void kernel_launch(void* const* d_in, const int* in_sizes, int n_in,
                              void* d_out, int out_size)
{
    const float* query  = (const float*)d_in[0];
    const float* key    = (const float*)d_in[1];
    const float* value  = (const float*)d_in[2];
    const float* mask   = (const float*)d_in[3];
    const float* adj    = (const float*)d_in[4];
    const float* lambdas= (const float*)d_in[5];
    const float* Wq     = (const float*)d_in[6];
    const float* bq     = (const float*)d_in[7];
    const float* Wk     = (const float*)d_in[8];
    const float* bk     = (const float*)d_in[9];
    const float* Wv     = (const float*)d_in[10];
    const float* bv     = (const float*)d_in[11];
    const float* Wo     = (const float*)d_in[12];
    const float* bo     = (const float*)d_in[13];
    float* out = (float*)d_out;

    void *pQ, *pK, *pV, *pVt, *pA, *pX, *pRS, *pPart;
    cudaGetSymbolAddress(&pQ, g_Q);
    cudaGetSymbolAddress(&pK, g_K);
    cudaGetSymbolAddress(&pV, g_V);
    cudaGetSymbolAddress(&pVt, g_Vt);
    cudaGetSymbolAddress(&pA, g_A);
    cudaGetSymbolAddress(&pX, g_X);
    cudaGetSymbolAddress(&pRS, g_rowsum);
    cudaGetSymbolAddress(&pPart, g_part);

    cudaFuncSetAttribute(flash_blend2, cudaFuncAttributeMaxDynamicSharedMemorySize, 75776);

    // Q/K/V projections: tf32x3 mma GEMM (M=3072, N=256, K=256)
    dim3 gP(2, NTOK / 128, 1);
    gemm_mma<<<gP, 256>>>(query, DMODEL, Wq, DMODEL, bq, (float*)pQ, 256, 0);
    gemm_mma<<<gP, 256>>>(key,   DMODEL, Wk, DMODEL, bk, (float*)pK, 256, 0);
    gemm_mma<<<gP, 256>>>(value, DMODEL, Wv, DMODEL, bv, (float*)pV, 256, 0);

    rowsum_kernel<<<NTOK, 256>>>(adj, (float*)pRS);

    // adj @ V: transpose V, tf32x3 mma GEMM split-K=4 (192 CTAs), reduce
    transpose_v<<<dim3(NTOK / 32, DMODEL / 32), dim3(32, 8)>>>((const float*)pV, (float*)pVt);
    dim3 gAV(2, NTOK / 128, 4);
    gemm_mma<<<gAV, 256>>>(adj, NTOK, (const float*)pVt, NTOK, nullptr,
                           (float*)pPart, 768, NTOK * DMODEL);
    reduce4_kernel<<<NTOK * DMODEL / 4 / 256, 256>>>((const float*)pPart, (float*)pA);

    dim3 gFlash(NTOK / 64, NHEAD);
    flash_blend2<<<gFlash, 256, 75776>>>((const float*)pQ, (const float*)pK, (const float*)pV,
                                         mask, (const float*)pA, (const float*)pRS,
                                         lambdas, (float*)pX);

    // output projection: tf32x3 mma GEMM
    gemm_mma<<<gP, 256>>>((const float*)pX, DMODEL, Wo, DMODEL, bo, out, 256, 0);
}

// round 7
// speedup vs baseline: 1.5680x; 1.1313x over previous
#include <cuda_runtime.h>
#include <math.h>
#include <stdint.h>

#define NTOK 3072
#define DMODEL 256
#define NHEAD 8
#define DK 32
#define EPSV 1e-6f

// ---------------- scratch ----------------
__device__ float g_Q[NTOK * DMODEL];
__device__ float g_K[NTOK * DMODEL];
__device__ float g_V[NTOK * DMODEL];
__device__ float g_Vt[DMODEL * NTOK];         // V transposed [256][3072]
__device__ float g_A[NTOK * DMODEL];          // adj @ V (after reduce)
__device__ float g_X[NTOK * DMODEL];
__device__ float g_rowsum[NTOK];
__device__ float g_part[4 * NTOK * DMODEL];   // split-K partials

// ================= mma helpers =================
__device__ __forceinline__ void mma_tf32(float* c, const uint32_t* a, const uint32_t* b)
{
    asm volatile(
        "mma.sync.aligned.m16n8k8.row.col.f32.tf32.tf32.f32 "
        "{%0,%1,%2,%3}, {%4,%5,%6,%7}, {%8,%9}, {%0,%1,%2,%3};"
        : "+f"(c[0]), "+f"(c[1]), "+f"(c[2]), "+f"(c[3])
        : "r"(a[0]), "r"(a[1]), "r"(a[2]), "r"(a[3]), "r"(b[0]), "r"(b[1]));
}

__device__ __forceinline__ float tf32_rna(float x)
{
    float y;
    asm("cvt.rna.tf32.f32 %0, %1;" : "=f"(y) : "f"(x));
    return y;
}

// x3 scheme: acc += ah*bl + al*bh + ah*bh (lo*lo dropped)
__device__ __forceinline__ void mma_x3(float* c, const uint32_t* ah, const uint32_t* al,
                                       const uint32_t* bh, const uint32_t* bl)
{
    mma_tf32(c, ah, bl);
    mma_tf32(c, al, bh);
    mma_tf32(c, ah, bh);
}

// ================= tf32x3 GEMM: C[M,256] = A[M,K] @ B[256,K]^T (+bias) =================
__global__ void __launch_bounds__(256) gemm_mma(const float* __restrict__ A, int lda,
                                                const float* __restrict__ B, int ldb,
                                                const float* __restrict__ bias,
                                                float* __restrict__ C,
                                                int kchunk, int part_stride)
{
    __shared__ float Ah[16][132];
    __shared__ float Al[16][132];
    __shared__ float Bh[16][132];
    __shared__ float Bl[16][132];
    const int tid = threadIdx.x;
    const int lane = tid & 31, wid = tid >> 5;
    const int wm = wid >> 2;
    const int wn = wid & 3;
    const int n0 = blockIdx.x * 128;
    const int m0 = blockIdx.y * 128;
    const int kbeg = blockIdx.z * kchunk;

    const int lr = tid >> 1;
    const int lc = (tid & 1) * 8;

    float acc[4][4][4] = {};

    for (int k0 = 0; k0 < kchunk; k0 += 16) {
        float av[8], bv[8];
        *(float4*)&av[0] = *(const float4*)(A + (size_t)(m0 + lr) * lda + kbeg + k0 + lc);
        *(float4*)&av[4] = *(const float4*)(A + (size_t)(m0 + lr) * lda + kbeg + k0 + lc + 4);
        *(float4*)&bv[0] = *(const float4*)(B + (size_t)(n0 + lr) * ldb + kbeg + k0 + lc);
        *(float4*)&bv[4] = *(const float4*)(B + (size_t)(n0 + lr) * ldb + kbeg + k0 + lc + 4);
        __syncthreads();
        #pragma unroll
        for (int j = 0; j < 8; j++) {
            float ah = tf32_rna(av[j]);
            float bh = tf32_rna(bv[j]);
            Ah[lc + j][lr] = ah; Al[lc + j][lr] = av[j] - ah;
            Bh[lc + j][lr] = bh; Bl[lc + j][lr] = bv[j] - bh;
        }
        __syncthreads();

        #pragma unroll
        for (int ks = 0; ks < 2; ks++) {
            const int kk = ks * 8 + (lane & 3);
            const int mrow = wm * 64 + (lane >> 2);
            const int ncol = wn * 32 + (lane >> 2);
            uint32_t ah[4][4], al[4][4], bh[4][2], bl[4][2];
            #pragma unroll
            for (int mt = 0; mt < 4; mt++) {
                ah[mt][0] = __float_as_uint(Ah[kk][mrow + mt * 16]);
                ah[mt][1] = __float_as_uint(Ah[kk][mrow + mt * 16 + 8]);
                ah[mt][2] = __float_as_uint(Ah[kk + 4][mrow + mt * 16]);
                ah[mt][3] = __float_as_uint(Ah[kk + 4][mrow + mt * 16 + 8]);
                al[mt][0] = __float_as_uint(Al[kk][mrow + mt * 16]);
                al[mt][1] = __float_as_uint(Al[kk][mrow + mt * 16 + 8]);
                al[mt][2] = __float_as_uint(Al[kk + 4][mrow + mt * 16]);
                al[mt][3] = __float_as_uint(Al[kk + 4][mrow + mt * 16 + 8]);
            }
            #pragma unroll
            for (int nt = 0; nt < 4; nt++) {
                bh[nt][0] = __float_as_uint(Bh[kk][ncol + nt * 8]);
                bh[nt][1] = __float_as_uint(Bh[kk + 4][ncol + nt * 8]);
                bl[nt][0] = __float_as_uint(Bl[kk][ncol + nt * 8]);
                bl[nt][1] = __float_as_uint(Bl[kk + 4][ncol + nt * 8]);
            }
            #pragma unroll
            for (int mt = 0; mt < 4; mt++)
                #pragma unroll
                for (int nt = 0; nt < 4; nt++)
                    mma_x3(acc[mt][nt], ah[mt], al[mt], bh[nt], bl[nt]);
        }
    }

    float* Cp = C + (size_t)blockIdx.z * part_stride;
    const int r0 = m0 + wm * 64 + (lane >> 2);
    const int c0 = n0 + wn * 32 + (lane & 3) * 2;
    #pragma unroll
    for (int nt = 0; nt < 4; nt++) {
        const int col = c0 + nt * 8;
        float2 bb = bias ? *(const float2*)(bias + col) : make_float2(0.f, 0.f);
        #pragma unroll
        for (int mt = 0; mt < 4; mt++) {
            const int row = r0 + mt * 16;
            *(float2*)(Cp + (size_t)row * DMODEL + col) =
                make_float2(acc[mt][nt][0] + bb.x, acc[mt][nt][1] + bb.y);
            *(float2*)(Cp + (size_t)(row + 8) * DMODEL + col) =
                make_float2(acc[mt][nt][2] + bb.x, acc[mt][nt][3] + bb.y);
        }
    }
}

// ================= transpose V -> Vt =================
__global__ void transpose_v(const float* __restrict__ src, float* __restrict__ dst)
{
    __shared__ float t[32][33];
    const int x0 = blockIdx.x * 32;
    const int y0 = blockIdx.y * 32;
    #pragma unroll
    for (int j = 0; j < 32; j += 8)
        t[threadIdx.y + j][threadIdx.x] =
            src[(size_t)(x0 + threadIdx.y + j) * DMODEL + y0 + threadIdx.x];
    __syncthreads();
    #pragma unroll
    for (int j = 0; j < 32; j += 8)
        dst[(size_t)(y0 + threadIdx.y + j) * NTOK + x0 + threadIdx.x] =
            t[threadIdx.x][threadIdx.y + j];
}

// ================= split-K reduce =================
__global__ void reduce4_kernel(const float* __restrict__ part, float* __restrict__ out)
{
    const int i = blockIdx.x * 256 + threadIdx.x;
    const int Q = NTOK * DMODEL / 4;
    const float4* p = (const float4*)part;
    float4 a = p[i], b = p[i + Q], c = p[i + 2 * Q], d = p[i + 3 * Q];
    float4 r;
    r.x = (a.x + b.x) + (c.x + d.x);
    r.y = (a.y + b.y) + (c.y + d.y);
    r.z = (a.z + b.z) + (c.z + d.z);
    r.w = (a.w + b.w) + (c.w + d.w);
    ((float4*)out)[i] = r;
}

// ================= adjacency row sums =================
__global__ void rowsum_kernel(const float* __restrict__ adj, float* __restrict__ out)
{
    const int row = blockIdx.x;
    const float4* p = (const float4*)(adj + (size_t)row * NTOK);
    float s = 0.f;
    for (int i = threadIdx.x; i < NTOK / 4; i += 256) {
        float4 v = p[i];
        s += (v.x + v.y) + (v.z + v.w);
    }
    #pragma unroll
    for (int o = 16; o; o >>= 1) s += __shfl_xor_sync(0xffffffffu, s, o);
    __shared__ float red[8];
    if ((threadIdx.x & 31) == 0) red[threadIdx.x >> 5] = s;
    __syncthreads();
    if (threadIdx.x < 8) {
        s = red[threadIdx.x];
        #pragma unroll
        for (int o = 4; o; o >>= 1) s += __shfl_xor_sync(0xffu, s, o);
        if (threadIdx.x == 0) out[row] = s;
    }
}

// ================= flash attention via mma (tf32x3) + lambda blend =================
// 64 q x 64 k tiles. 8 warps. QK: warps 4m x 2n (warp tile 16x32).
// PV: warps 4m x 2n over O[64,32] (warp tile 16x16). 47104 B static smem, 3 CTAs/SM.
__global__ void __launch_bounds__(256, 3)
flash_mma(const float* __restrict__ Q, const float* __restrict__ K,
          const float* __restrict__ V, const float* __restrict__ mask,
          const float* __restrict__ A, const float* __restrict__ rowsum,
          const float* __restrict__ lambdas, float* __restrict__ X)
{
    __shared__ float Qs[64][36];   // [row][k]    banks 4r+k  (36 % 32 == 4)
    __shared__ float Ks[64][40];   // [key][k]    banks 8n+k  (40 % 32 == 8)
    __shared__ float Vs[64][40];   // [key][dim]  banks 8k+n
    __shared__ float Ps[64][68];   // [row][col]; cols 64..66 = m / l / alpha

    const int h  = blockIdx.y;
    const int q0 = blockIdx.x * 64;
    const int tid = threadIdx.x;
    const int lane = tid & 31, wid = tid >> 5;
    const int qr = lane >> 2;          // quad row 0..7
    const int qc = lane & 3;           // quad col 0..3
    const float scale = 0.17677669529663687f;   // 1/sqrt(32)

    // load Q tile (64 x 32)
    #pragma unroll
    for (int it = 0; it < 2; it++) {
        int i = tid + it * 256;
        int r = i >> 3, c = (i & 7) * 4;
        *(float4*)&Qs[r][c] = *(const float4*)(Q + (size_t)(q0 + r) * DMODEL + h * DK + c);
    }
    if (tid < 64) { Ps[tid][64] = -1e30f; Ps[tid][65] = 0.f; }

    // QK warp layout: wmq = wid>>1 (m16 block), wnq = wid&1 (n32 block)
    const int wmq = wid >> 1, wnq = wid & 1;
    // PV warp layout: same split; O warp tile 16 rows x 16 dims
    const int r1 = wmq * 16 + qr;      // PV/epilogue rows r1, r1+8

    float oacc[2][4] = {};             // nt=2 (dims), m16n8 acc

    for (int kt = 0; kt < NTOK / 64; kt++) {
        const int k0 = kt * 64;
        __syncthreads();
        // load K, V tiles (64 x 32 each)
        #pragma unroll
        for (int it = 0; it < 2; it++) {
            int i = tid + it * 256;
            int r = i >> 3, c = (i & 7) * 4;
            *(float4*)&Ks[r][c] = *(const float4*)(K + (size_t)(k0 + r) * DMODEL + h * DK + c);
            *(float4*)&Vs[r][c] = *(const float4*)(V + (size_t)(k0 + r) * DMODEL + h * DK + c);
        }
        __syncthreads();

        // ---- QK^T: S[64][64], warp tile 16x32 ----
        float sacc[4][4] = {};
        #pragma unroll
        for (int ks = 0; ks < 4; ks++) {
            const int kk = ks * 8 + qc;
            uint32_t ah[4], al[4];
            {
                float a0 = Qs[wmq * 16 + qr][kk];
                float a1 = Qs[wmq * 16 + qr + 8][kk];
                float a2 = Qs[wmq * 16 + qr][kk + 4];
                float a3 = Qs[wmq * 16 + qr + 8][kk + 4];
                float h0 = tf32_rna(a0), h1 = tf32_rna(a1), h2 = tf32_rna(a2), h3 = tf32_rna(a3);
                ah[0] = __float_as_uint(h0); al[0] = __float_as_uint(a0 - h0);
                ah[1] = __float_as_uint(h1); al[1] = __float_as_uint(a1 - h1);
                ah[2] = __float_as_uint(h2); al[2] = __float_as_uint(a2 - h2);
                ah[3] = __float_as_uint(h3); al[3] = __float_as_uint(a3 - h3);
            }
            #pragma unroll
            for (int nt = 0; nt < 4; nt++) {
                const int nrow = wnq * 32 + nt * 8 + qr;
                float b0 = Ks[nrow][kk];
                float b1 = Ks[nrow][kk + 4];
                float h0 = tf32_rna(b0), h1 = tf32_rna(b1);
                uint32_t bh[2] = { __float_as_uint(h0), __float_as_uint(h1) };
                uint32_t bl[2] = { __float_as_uint(b0 - h0), __float_as_uint(b1 - h1) };
                mma_x3(sacc[nt], ah, al, bh, bl);
            }
        }
        // write scaled S to Ps
        #pragma unroll
        for (int nt = 0; nt < 4; nt++) {
            const int col = wnq * 32 + nt * 8 + qc * 2;
            const int row = wmq * 16 + qr;
            *(float2*)&Ps[row][col]     = make_float2(sacc[nt][0] * scale, sacc[nt][1] * scale);
            *(float2*)&Ps[row + 8][col] = make_float2(sacc[nt][2] * scale, sacc[nt][3] * scale);
        }
        __syncthreads();

        // ---- softmax (SIMT): warp wid handles rows wid*8 .. wid*8+7 ----
        #pragma unroll
        for (int rr = 0; rr < 8; rr++) {
            const int row = wid * 8 + rr;
            const float* mrow = mask + (size_t)(q0 + row) * NTOK + k0;
            float s0 = Ps[row][lane]      + mrow[lane];
            float s1 = Ps[row][lane + 32] + mrow[lane + 32];
            float mx = fmaxf(s0, s1);
            #pragma unroll
            for (int off = 16; off; off >>= 1)
                mx = fmaxf(mx, __shfl_xor_sync(0xffffffffu, mx, off));
            const float mo = Ps[row][64];
            const float mn = fmaxf(mo, mx);
            float p0 = __expf(s0 - mn), p1 = __expf(s1 - mn);
            Ps[row][lane] = p0; Ps[row][lane + 32] = p1;
            float ps = p0 + p1;
            #pragma unroll
            for (int off = 16; off; off >>= 1)
                ps += __shfl_xor_sync(0xffffffffu, ps, off);
            if (lane == 0) {
                float al = __expf(mo - mn);
                Ps[row][65] = Ps[row][65] * al + ps;
                Ps[row][64] = mn;
                Ps[row][66] = al;
            }
        }
        __syncthreads();

        // ---- PV: O[64][32] += P[64x64] @ V[64x32], warp tile 16x16 ----
        {
            const float al1 = Ps[r1][66], al2 = Ps[r1 + 8][66];
            #pragma unroll
            for (int nt = 0; nt < 2; nt++) {
                oacc[nt][0] *= al1; oacc[nt][1] *= al1;
                oacc[nt][2] *= al2; oacc[nt][3] *= al2;
            }
        }
        #pragma unroll
        for (int ks = 0; ks < 8; ks++) {
            const int kk = ks * 8 + qc;
            uint32_t ah[4], al[4];
            {
                float a0 = Ps[r1][kk];
                float a1 = Ps[r1 + 8][kk];
                float a2 = Ps[r1][kk + 4];
                float a3 = Ps[r1 + 8][kk + 4];
                float h0 = tf32_rna(a0), h1 = tf32_rna(a1), h2 = tf32_rna(a2), h3 = tf32_rna(a3);
                ah[0] = __float_as_uint(h0); al[0] = __float_as_uint(a0 - h0);
                ah[1] = __float_as_uint(h1); al[1] = __float_as_uint(a1 - h1);
                ah[2] = __float_as_uint(h2); al[2] = __float_as_uint(a2 - h2);
                ah[3] = __float_as_uint(h3); al[3] = __float_as_uint(a3 - h3);
            }
            #pragma unroll
            for (int nt = 0; nt < 2; nt++) {
                const int dcol = wnq * 16 + nt * 8 + qr;
                float b0 = Vs[kk][dcol];
                float b1 = Vs[kk + 4][dcol];
                float h0 = tf32_rna(b0), h1 = tf32_rna(b1);
                uint32_t bh[2] = { __float_as_uint(h0), __float_as_uint(h1) };
                uint32_t bl[2] = { __float_as_uint(b0 - h0), __float_as_uint(b1 - h1) };
                mma_x3(oacc[nt], ah, al, bh, bl);
            }
        }
    }

    // ---- epilogue: normalize + lambda blend ----
    const float lam0 = lambdas[0], lam1 = lambdas[1];
    const float invl1 = lam0 / Ps[r1][65];
    const float invl2 = lam0 / Ps[r1 + 8][65];
    const int row1 = q0 + r1, row2 = row1 + 8;
    const float invd1 = lam1 / (rowsum[row1] + EPSV);
    const float invd2 = lam1 / (rowsum[row2] + EPSV);
    #pragma unroll
    for (int nt = 0; nt < 2; nt++) {
        const int col = h * DK + wnq * 16 + nt * 8 + qc * 2;
        float2 a1v = *(const float2*)(A + (size_t)row1 * DMODEL + col);
        float2 a2v = *(const float2*)(A + (size_t)row2 * DMODEL + col);
        *(float2*)(X + (size_t)row1 * DMODEL + col) =
            make_float2(oacc[nt][0] * invl1 + a1v.x * invd1,
                        oacc[nt][1] * invl1 + a1v.y * invd1);
        *(float2*)(X + (size_t)row2 * DMODEL + col) =
            make_float2(oacc[nt][2] * invl2 + a2v.x * invd2,
                        oacc[nt][3] * invl2 + a2v.y * invd2);
    }
}

// ================= launch =================
extern "C" void kernel_launch(void* const* d_in, const int* in_sizes, int n_in,
                              void* d_out, int out_size)
{
    const float* query  = (const float*)d_in[0];
    const float* key    = (const float*)d_in[1];
    const float* value  = (const float*)d_in[2];
    const float* mask   = (const float*)d_in[3];
    const float* adj    = (const float*)d_in[4];
    const float* lambdas= (const float*)d_in[5];
    const float* Wq     = (const float*)d_in[6];
    const float* bq     = (const float*)d_in[7];
    const float* Wk     = (const float*)d_in[8];
    const float* bk     = (const float*)d_in[9];
    const float* Wv     = (const float*)d_in[10];
    const float* bv     = (const float*)d_in[11];
    const float* Wo     = (const float*)d_in[12];
    const float* bo     = (const float*)d_in[13];
    float* out = (float*)d_out;

    void *pQ, *pK, *pV, *pVt, *pA, *pX, *pRS, *pPart;
    cudaGetSymbolAddress(&pQ, g_Q);
    cudaGetSymbolAddress(&pK, g_K);
    cudaGetSymbolAddress(&pV, g_V);
    cudaGetSymbolAddress(&pVt, g_Vt);
    cudaGetSymbolAddress(&pA, g_A);
    cudaGetSymbolAddress(&pX, g_X);
    cudaGetSymbolAddress(&pRS, g_rowsum);
    cudaGetSymbolAddress(&pPart, g_part);

    // Q/K/V projections: tf32x3 mma GEMM (M=3072, N=256, K=256)
    dim3 gP(2, NTOK / 128, 1);
    gemm_mma<<<gP, 256>>>(query, DMODEL, Wq, DMODEL, bq, (float*)pQ, 256, 0);
    gemm_mma<<<gP, 256>>>(key,   DMODEL, Wk, DMODEL, bk, (float*)pK, 256, 0);
    gemm_mma<<<gP, 256>>>(value, DMODEL, Wv, DMODEL, bv, (float*)pV, 256, 0);

    rowsum_kernel<<<NTOK, 256>>>(adj, (float*)pRS);

    // adj @ V: transpose V, tf32x3 mma GEMM split-K=4 (192 CTAs), reduce
    transpose_v<<<dim3(NTOK / 32, DMODEL / 32), dim3(32, 8)>>>((const float*)pV, (float*)pVt);
    dim3 gAV(2, NTOK / 128, 4);
    gemm_mma<<<gAV, 256>>>(adj, NTOK, (const float*)pVt, NTOK, nullptr,
                           (float*)pPart, 768, NTOK * DMODEL);
    reduce4_kernel<<<NTOK * DMODEL / 4 / 256, 256>>>((const float*)pPart, (float*)pA);

    dim3 gFlash(NTOK / 64, NHEAD);
    flash_mma<<<gFlash, 256>>>((const float*)pQ, (const float*)pK, (const float*)pV,
                               mask, (const float*)pA, (const float*)pRS,
                               lambdas, (float*)pX);

    // output projection: tf32x3 mma GEMM
    gemm_mma<<<gP, 256>>>((const float*)pX, DMODEL, Wo, DMODEL, bo, out, 256, 0);
}

// round 8
// speedup vs baseline: 1.9540x; 1.2462x over previous
#include <cuda_runtime.h>
#include <math.h>
#include <stdint.h>

#define NTOK 3072
#define DMODEL 256
#define NHEAD 8
#define DK 32
#define EPSV 1e-6f

// ---------------- scratch ----------------
__device__ float g_Q[NTOK * DMODEL];
__device__ float g_K[NTOK * DMODEL];
__device__ float g_V[NTOK * DMODEL];
__device__ float g_Vt[DMODEL * NTOK];         // V transposed [256][3072]
__device__ float g_X[NTOK * DMODEL];
__device__ float g_rowsum[NTOK];
__device__ float g_part[4 * NTOK * DMODEL];   // adjV split-K partials

// ================= mma helpers =================
__device__ __forceinline__ void mma_tf32(float* c, const uint32_t* a, const uint32_t* b)
{
    asm volatile(
        "mma.sync.aligned.m16n8k8.row.col.f32.tf32.tf32.f32 "
        "{%0,%1,%2,%3}, {%4,%5,%6,%7}, {%8,%9}, {%0,%1,%2,%3};"
        : "+f"(c[0]), "+f"(c[1]), "+f"(c[2]), "+f"(c[3])
        : "r"(a[0]), "r"(a[1]), "r"(a[2]), "r"(a[3]), "r"(b[0]), "r"(b[1]));
}

__device__ __forceinline__ float tf32_rna(float x)
{
    float y;
    asm("cvt.rna.tf32.f32 %0, %1;" : "=f"(y) : "f"(x));
    return y;
}

__device__ __forceinline__ uint32_t fau(float x) { return __float_as_uint(x); }

__device__ __forceinline__ void mma_x3(float* c, const uint32_t* ah, const uint32_t* al,
                                       const uint32_t* bh, const uint32_t* bl)
{
    mma_tf32(c, ah, bl);
    mma_tf32(c, al, bh);
    mma_tf32(c, ah, bh);
}

// ================= tf32x3 GEMM core =================
// C[128,128-tile] = A[M,K] @ B[N,K]^T (+bias). Pre-split (hi,lo) float2 smem,
// stride 20 -> conflict-free 64-bit fragment loads. 8 warps 2m x 4n, 64x32 warp tile.
__device__ __forceinline__ void gemm_core(const float* __restrict__ A, int lda,
                                          const float* __restrict__ B, int ldb,
                                          const float* __restrict__ bias,
                                          float* __restrict__ C,
                                          int kchunk, int kbeg, int m0, int n0,
                                          float2 (*A2)[20], float2 (*B2)[20])
{
    const int tid = threadIdx.x;
    const int lane = tid & 31, wid = tid >> 5;
    const int qr = lane >> 2, qc = lane & 3;
    const int wm = wid >> 2;          // 0..1
    const int wn = wid & 3;           // 0..3
    const int lr = tid >> 1;          // 0..127
    const int lc = (tid & 1) * 8;     // 0 or 8

    float acc[4][4][4] = {};

    for (int k0 = 0; k0 < kchunk; k0 += 16) {
        float av[8], bv[8];
        *(float4*)&av[0] = *(const float4*)(A + (size_t)(m0 + lr) * lda + kbeg + k0 + lc);
        *(float4*)&av[4] = *(const float4*)(A + (size_t)(m0 + lr) * lda + kbeg + k0 + lc + 4);
        *(float4*)&bv[0] = *(const float4*)(B + (size_t)(n0 + lr) * ldb + kbeg + k0 + lc);
        *(float4*)&bv[4] = *(const float4*)(B + (size_t)(n0 + lr) * ldb + kbeg + k0 + lc + 4);
        __syncthreads();
        #pragma unroll
        for (int j = 0; j < 8; j += 2) {
            float ah0 = tf32_rna(av[j]),     bh0 = tf32_rna(bv[j]);
            float ah1 = tf32_rna(av[j + 1]), bh1 = tf32_rna(bv[j + 1]);
            *(float4*)&A2[lr][lc + j] = make_float4(ah0, av[j] - ah0, ah1, av[j + 1] - ah1);
            *(float4*)&B2[lr][lc + j] = make_float4(bh0, bv[j] - bh0, bh1, bv[j + 1] - bh1);
        }
        __syncthreads();

        #pragma unroll
        for (int ks = 0; ks < 2; ks++) {
            const int kk = ks * 8 + qc;
            uint32_t ah[4][4], al[4][4], bh[4][2], bl[4][2];
            #pragma unroll
            for (int mt = 0; mt < 4; mt++) {
                const int mrow = wm * 64 + mt * 16 + qr;
                float2 v0 = A2[mrow][kk];
                float2 v1 = A2[mrow + 8][kk];
                float2 v2 = A2[mrow][kk + 4];
                float2 v3 = A2[mrow + 8][kk + 4];
                ah[mt][0] = fau(v0.x); al[mt][0] = fau(v0.y);
                ah[mt][1] = fau(v1.x); al[mt][1] = fau(v1.y);
                ah[mt][2] = fau(v2.x); al[mt][2] = fau(v2.y);
                ah[mt][3] = fau(v3.x); al[mt][3] = fau(v3.y);
            }
            #pragma unroll
            for (int nt = 0; nt < 4; nt++) {
                const int ncol = wn * 32 + nt * 8 + qr;
                float2 w0 = B2[ncol][kk];
                float2 w1 = B2[ncol][kk + 4];
                bh[nt][0] = fau(w0.x); bl[nt][0] = fau(w0.y);
                bh[nt][1] = fau(w1.x); bl[nt][1] = fau(w1.y);
            }
            #pragma unroll
            for (int mt = 0; mt < 4; mt++)
                #pragma unroll
                for (int nt = 0; nt < 4; nt++)
                    mma_x3(acc[mt][nt], ah[mt], al[mt], bh[nt], bl[nt]);
        }
    }

    const int r0 = m0 + wm * 64 + qr;
    const int c0 = n0 + wn * 32 + qc * 2;
    #pragma unroll
    for (int nt = 0; nt < 4; nt++) {
        const int col = c0 + nt * 8;
        float2 bb = bias ? *(const float2*)(bias + col) : make_float2(0.f, 0.f);
        #pragma unroll
        for (int mt = 0; mt < 4; mt++) {
            const int row = r0 + mt * 16;
            *(float2*)(C + (size_t)row * DMODEL + col) =
                make_float2(acc[mt][nt][0] + bb.x, acc[mt][nt][1] + bb.y);
            *(float2*)(C + (size_t)(row + 8) * DMODEL + col) =
                make_float2(acc[mt][nt][2] + bb.x, acc[mt][nt][3] + bb.y);
        }
    }
}

// batched Q/K/V projection: blockIdx.z selects input/weight/bias/output
__global__ void __launch_bounds__(256)
gemm_qkv(const float* q, const float* k, const float* v,
         const float* Wq, const float* Wk, const float* Wv,
         const float* bq, const float* bk, const float* bv,
         float* Cq, float* Ck, float* Cv)
{
    __shared__ float2 A2[128][20];
    __shared__ float2 B2[128][20];
    const int z = blockIdx.z;
    const float* A = (z == 0) ? q : (z == 1) ? k : v;
    const float* W = (z == 0) ? Wq : (z == 1) ? Wk : Wv;
    const float* bb = (z == 0) ? bq : (z == 1) ? bk : bv;
    float* C = (z == 0) ? Cq : (z == 1) ? Ck : Cv;
    gemm_core(A, DMODEL, W, DMODEL, bb, C, 256, 0,
              blockIdx.y * 128, blockIdx.x * 128, A2, B2);
}

// generic: adjV split-K (z slices) and output projection
__global__ void __launch_bounds__(256)
gemm_mma2(const float* __restrict__ A, int lda, const float* __restrict__ B, int ldb,
          const float* __restrict__ bias, float* __restrict__ C,
          int kchunk, int part_stride)
{
    __shared__ float2 A2[128][20];
    __shared__ float2 B2[128][20];
    gemm_core(A, lda, B, ldb, bias, C + (size_t)blockIdx.z * part_stride,
              kchunk, blockIdx.z * kchunk, blockIdx.y * 128, blockIdx.x * 128, A2, B2);
}

// ================= transpose V -> Vt =================
__global__ void transpose_v(const float* __restrict__ src, float* __restrict__ dst)
{
    __shared__ float t[32][33];
    const int x0 = blockIdx.x * 32;
    const int y0 = blockIdx.y * 32;
    #pragma unroll
    for (int j = 0; j < 32; j += 8)
        t[threadIdx.y + j][threadIdx.x] =
            src[(size_t)(x0 + threadIdx.y + j) * DMODEL + y0 + threadIdx.x];
    __syncthreads();
    #pragma unroll
    for (int j = 0; j < 32; j += 8)
        dst[(size_t)(y0 + threadIdx.y + j) * NTOK + x0 + threadIdx.x] =
            t[threadIdx.x][threadIdx.y + j];
}

// ================= adjacency row sums =================
__global__ void rowsum_kernel(const float* __restrict__ adj, float* __restrict__ out)
{
    const int row = blockIdx.x;
    const float4* p = (const float4*)(adj + (size_t)row * NTOK);
    float s = 0.f;
    for (int i = threadIdx.x; i < NTOK / 4; i += 256) {
        float4 v = p[i];
        s += (v.x + v.y) + (v.z + v.w);
    }
    #pragma unroll
    for (int o = 16; o; o >>= 1) s += __shfl_xor_sync(0xffffffffu, s, o);
    __shared__ float red[8];
    if ((threadIdx.x & 31) == 0) red[threadIdx.x >> 5] = s;
    __syncthreads();
    if (threadIdx.x < 8) {
        s = red[threadIdx.x];
        #pragma unroll
        for (int o = 4; o; o >>= 1) s += __shfl_xor_sync(0xffu, s, o);
        if (threadIdx.x == 0) out[row] = s;
    }
}

// ================= flash attention (QK x1, PV x3, no-max softmax) =================
// 64 q x 64 k tiles, 8 warps (2m x 2n). Dyn smem 71936 B -> 3 CTAs/SM.
#define QS(r, c)  Qs[(r) * 36 + (c)]
#define KS(r, c)  Ks[(r) * 36 + (c)]
#define VS(r, c)  Vs[(r) * 36 + (c)]
#define PS(r, c)  Ps2[(r) * 68 + (c)]

__global__ void __launch_bounds__(256, 3)
flash_mma2(const float* __restrict__ Q, const float* __restrict__ K,
           const float* __restrict__ V, const float* __restrict__ mask,
           const float* __restrict__ part, const float* __restrict__ rowsum,
           const float* __restrict__ lambdas, float* __restrict__ X)
{
    extern __shared__ float smf[];
    float*  Qs  = smf;                        // [64][36] fp32 (tf32-rounded)
    float*  Ks  = Qs + 2304;                  // [64][36] fp32 (tf32-rounded)
    float2* Vs  = (float2*)(Ks + 2304);       // [64][36] (hi,lo)
    float2* Ps2 = Vs + 2304;                  // [64][68] (hi,lo)
    float*  l_sh = (float*)(Ps2 + 4352);      // [64]

    const int h  = blockIdx.y;
    const int q0 = blockIdx.x * 64;
    const int tid = threadIdx.x;
    const int lane = tid & 31, wid = tid >> 5;
    const int qr = lane >> 2, qc = lane & 3;
    const int wmq = wid >> 1, wnq = wid & 1;
    const int r1 = wmq * 16 + qr;
    const float scale = 0.17677669529663687f;   // 1/sqrt(32)

    // load Q tile (tf32-rounded)
    #pragma unroll
    for (int it = 0; it < 2; it++) {
        int i = tid + it * 256;
        int r = i >> 3, c = (i & 7) * 4;
        float4 v = *(const float4*)(Q + (size_t)(q0 + r) * DMODEL + h * DK + c);
        *(float4*)&QS(r, c) = make_float4(tf32_rna(v.x), tf32_rna(v.y),
                                          tf32_rna(v.z), tf32_rna(v.w));
    }
    if (tid < 64) l_sh[tid] = 0.f;

    float oacc[2][4] = {};

    for (int kt = 0; kt < NTOK / 64; kt++) {
        const int k0 = kt * 64;
        __syncthreads();   // prev PV done with Ps2/Vs; QK done with Ks
        // load K (rounded) and V (hi,lo split)
        #pragma unroll
        for (int it = 0; it < 2; it++) {
            int i = tid + it * 256;
            int r = i >> 3, c = (i & 7) * 4;
            float4 kv = *(const float4*)(K + (size_t)(k0 + r) * DMODEL + h * DK + c);
            *(float4*)&KS(r, c) = make_float4(tf32_rna(kv.x), tf32_rna(kv.y),
                                              tf32_rna(kv.z), tf32_rna(kv.w));
            float4 vv = *(const float4*)(V + (size_t)(k0 + r) * DMODEL + h * DK + c);
            float h0 = tf32_rna(vv.x), h1 = tf32_rna(vv.y);
            float h2 = tf32_rna(vv.z), h3 = tf32_rna(vv.w);
            *(float4*)&VS(r, c)     = make_float4(h0, vv.x - h0, h1, vv.y - h1);
            *(float4*)&VS(r, c + 2) = make_float4(h2, vv.z - h2, h3, vv.w - h3);
        }
        __syncthreads();

        // ---- QK^T (single tf32): warp tile 16x32 ----
        float sacc[4][4] = {};
        #pragma unroll
        for (int ks = 0; ks < 4; ks++) {
            const int kk = ks * 8 + qc;
            uint32_t a[4] = { fau(QS(r1, kk)), fau(QS(r1 + 8, kk)),
                              fau(QS(r1, kk + 4)), fau(QS(r1 + 8, kk + 4)) };
            #pragma unroll
            for (int nt = 0; nt < 4; nt++) {
                const int nrow = wnq * 32 + nt * 8 + qr;
                uint32_t b[2] = { fau(KS(nrow, kk)), fau(KS(nrow, kk + 4)) };
                mma_tf32(sacc[nt], a, b);
            }
        }

        // ---- exp + mask in registers; row sums; write P(hi,lo) ----
        float ps1 = 0.f, ps2 = 0.f;
        #pragma unroll
        for (int nt = 0; nt < 4; nt++) {
            const int colb = wnq * 32 + nt * 8 + qc * 2;
            const float* mp = mask + (size_t)(q0 + r1) * NTOK + k0 + colb;
            float2 m1 = *(const float2*)mp;
            float2 m2 = *(const float2*)(mp + 8 * NTOK);
            float p0 = __expf(fmaf(sacc[nt][0], scale, m1.x));
            float p1 = __expf(fmaf(sacc[nt][1], scale, m1.y));
            float p2 = __expf(fmaf(sacc[nt][2], scale, m2.x));
            float p3 = __expf(fmaf(sacc[nt][3], scale, m2.y));
            ps1 += p0 + p1;
            ps2 += p2 + p3;
            float h0 = tf32_rna(p0), h1 = tf32_rna(p1);
            float h2 = tf32_rna(p2), h3 = tf32_rna(p3);
            *(float4*)&PS(r1, colb)     = make_float4(h0, p0 - h0, h1, p1 - h1);
            *(float4*)&PS(r1 + 8, colb) = make_float4(h2, p2 - h2, h3, p3 - h3);
        }
        ps1 += __shfl_xor_sync(0xffffffffu, ps1, 1);
        ps1 += __shfl_xor_sync(0xffffffffu, ps1, 2);
        ps2 += __shfl_xor_sync(0xffffffffu, ps2, 1);
        ps2 += __shfl_xor_sync(0xffffffffu, ps2, 2);
        if (qc == 0) {
            atomicAdd(&l_sh[r1], ps1);
            atomicAdd(&l_sh[r1 + 8], ps2);
        }
        __syncthreads();   // Ps2 complete

        // ---- PV (x3): O[64][32] += P @ V, warp tile 16x16 ----
        #pragma unroll
        for (int ks = 0; ks < 8; ks++) {
            const int kk = ks * 8 + qc;
            float2 p0 = PS(r1, kk);
            float2 p1 = PS(r1 + 8, kk);
            float2 p2 = PS(r1, kk + 4);
            float2 p3 = PS(r1 + 8, kk + 4);
            uint32_t ah[4] = { fau(p0.x), fau(p1.x), fau(p2.x), fau(p3.x) };
            uint32_t al[4] = { fau(p0.y), fau(p1.y), fau(p2.y), fau(p3.y) };
            #pragma unroll
            for (int nt = 0; nt < 2; nt++) {
                const int dcol = wnq * 16 + nt * 8 + qr;
                float2 b0 = VS(kk, dcol);
                float2 b1 = VS(kk + 4, dcol);
                uint32_t bh[2] = { fau(b0.x), fau(b1.x) };
                uint32_t bl[2] = { fau(b0.y), fau(b1.y) };
                mma_x3(oacc[nt], ah, al, bh, bl);
            }
        }
    }
    __syncthreads();   // l_sh complete

    // ---- epilogue: normalize + lambda blend (sum 4 adjV partials inline) ----
    const float lam0 = lambdas[0], lam1 = lambdas[1];
    const int row1 = q0 + r1, row2 = row1 + 8;
    const float invl1 = lam0 / l_sh[r1];
    const float invl2 = lam0 / l_sh[r1 + 8];
    const float invd1 = lam1 / (rowsum[row1] + EPSV);
    const float invd2 = lam1 / (rowsum[row2] + EPSV);
    const int NM = NTOK * DMODEL;
    #pragma unroll
    for (int nt = 0; nt < 2; nt++) {
        const int col = h * DK + wnq * 16 + nt * 8 + qc * 2;
        float ax1 = 0.f, ay1 = 0.f, ax2 = 0.f, ay2 = 0.f;
        #pragma unroll
        for (int z = 0; z < 4; z++) {
            float2 a1 = *(const float2*)(part + (size_t)z * NM + (size_t)row1 * DMODEL + col);
            float2 a2 = *(const float2*)(part + (size_t)z * NM + (size_t)row2 * DMODEL + col);
            ax1 += a1.x; ay1 += a1.y; ax2 += a2.x; ay2 += a2.y;
        }
        *(float2*)(X + (size_t)row1 * DMODEL + col) =
            make_float2(oacc[nt][0] * invl1 + ax1 * invd1,
                        oacc[nt][1] * invl1 + ay1 * invd1);
        *(float2*)(X + (size_t)row2 * DMODEL + col) =
            make_float2(oacc[nt][2] * invl2 + ax2 * invd2,
                        oacc[nt][3] * invl2 + ay2 * invd2);
    }
}

// ================= launch =================
extern "C" void kernel_launch(void* const* d_in, const int* in_sizes, int n_in,
                              void* d_out, int out_size)
{
    const float* query  = (const float*)d_in[0];
    const float* key    = (const float*)d_in[1];
    const float* value  = (const float*)d_in[2];
    const float* mask   = (const float*)d_in[3];
    const float* adj    = (const float*)d_in[4];
    const float* lambdas= (const float*)d_in[5];
    const float* Wq     = (const float*)d_in[6];
    const float* bq     = (const float*)d_in[7];
    const float* Wk     = (const float*)d_in[8];
    const float* bk     = (const float*)d_in[9];
    const float* Wv     = (const float*)d_in[10];
    const float* bv     = (const float*)d_in[11];
    const float* Wo     = (const float*)d_in[12];
    const float* bo     = (const float*)d_in[13];
    float* out = (float*)d_out;

    void *pQ, *pK, *pV, *pVt, *pX, *pRS, *pPart;
    cudaGetSymbolAddress(&pQ, g_Q);
    cudaGetSymbolAddress(&pK, g_K);
    cudaGetSymbolAddress(&pV, g_V);
    cudaGetSymbolAddress(&pVt, g_Vt);
    cudaGetSymbolAddress(&pX, g_X);
    cudaGetSymbolAddress(&pRS, g_rowsum);
    cudaGetSymbolAddress(&pPart, g_part);

    const int flash_smem = 71936;
    cudaFuncSetAttribute(flash_mma2, cudaFuncAttributeMaxDynamicSharedMemorySize, flash_smem);

    // batched Q/K/V projections: 144 CTAs, one wave
    dim3 gQKV(2, NTOK / 128, 3);
    gemm_qkv<<<gQKV, 256>>>(query, key, value, Wq, Wk, Wv, bq, bk, bv,
                            (float*)pQ, (float*)pK, (float*)pV);

    rowsum_kernel<<<NTOK, 256>>>(adj, (float*)pRS);

    // adj @ V: transpose, split-K=4 GEMM (partials summed in flash epilogue)
    transpose_v<<<dim3(NTOK / 32, DMODEL / 32), dim3(32, 8)>>>((const float*)pV, (float*)pVt);
    dim3 gAV(2, NTOK / 128, 4);
    gemm_mma2<<<gAV, 256>>>(adj, NTOK, (const float*)pVt, NTOK, nullptr,
                            (float*)pPart, 768, NTOK * DMODEL);

    dim3 gFlash(NTOK / 64, NHEAD);
    flash_mma2<<<gFlash, 256, flash_smem>>>((const float*)pQ, (const float*)pK, (const float*)pV,
                                            mask, (const float*)pPart, (const float*)pRS,
                                            lambdas, (float*)pX);

    // output projection
    dim3 gO(2, NTOK / 128, 1);
    gemm_mma2<<<gO, 256>>>((const float*)pX, DMODEL, Wo, DMODEL, bo, out, 256, 0);
}

// round 9
// speedup vs baseline: 2.2562x; 1.1547x over previous
#include <cuda_runtime.h>
#include <math.h>
#include <stdint.h>

#define NTOK 3072
#define DMODEL 256
#define NHEAD 8
#define DK 32
#define EPSV 1e-6f
#define SPLITK_ADJ 6

// ---------------- scratch ----------------
__device__ float g_Q[NTOK * DMODEL];
__device__ float g_K[NTOK * DMODEL];
__device__ float g_V[NTOK * DMODEL];
__device__ float g_Vt[DMODEL * NTOK];                 // V transposed [256][3072]
__device__ float g_X[NTOK * DMODEL];
__device__ float g_rowsum[NTOK];
__device__ float g_part[SPLITK_ADJ * NTOK * DMODEL];  // split-K partials (adjV / out-proj)

// ================= mma helpers =================
__device__ __forceinline__ void mma_tf32(float* c, const uint32_t* a, const uint32_t* b)
{
    asm volatile(
        "mma.sync.aligned.m16n8k8.row.col.f32.tf32.tf32.f32 "
        "{%0,%1,%2,%3}, {%4,%5,%6,%7}, {%8,%9}, {%0,%1,%2,%3};"
        : "+f"(c[0]), "+f"(c[1]), "+f"(c[2]), "+f"(c[3])
        : "r"(a[0]), "r"(a[1]), "r"(a[2]), "r"(a[3]), "r"(b[0]), "r"(b[1]));
}

__device__ __forceinline__ float tf32_rna(float x)
{
    float y;
    asm("cvt.rna.tf32.f32 %0, %1;" : "=f"(y) : "f"(x));
    return y;
}

__device__ __forceinline__ uint32_t fau(float x) { return __float_as_uint(x); }

__device__ __forceinline__ void mma_x3(float* c, const uint32_t* ah, const uint32_t* al,
                                       const uint32_t* bh, const uint32_t* bl)
{
    mma_tf32(c, ah, bl);
    mma_tf32(c, al, bh);
    mma_tf32(c, ah, bh);
}

__device__ __forceinline__ void split_store8(float2* dstA, float2* dstB,
                                             const float* av, const float* bv)
{
    #pragma unroll
    for (int j = 0; j < 8; j += 2) {
        float ah0 = tf32_rna(av[j]),     bh0 = tf32_rna(bv[j]);
        float ah1 = tf32_rna(av[j + 1]), bh1 = tf32_rna(bv[j + 1]);
        *(float4*)&dstA[j] = make_float4(ah0, av[j] - ah0, ah1, av[j + 1] - ah1);
        *(float4*)&dstB[j] = make_float4(bh0, bv[j] - bh0, bh1, bv[j + 1] - bh1);
    }
}

// ================= pipelined tf32x3 GEMM core =================
// C[128,128-tile] = A[M,K] @ B[N,K]^T (+bias). Double-buffered (hi,lo) smem,
// one __syncthreads per 16-K iteration; gmem prefetch hidden under MMA phase.
__device__ __forceinline__ void gemm_core(const float* __restrict__ A, int lda,
                                          const float* __restrict__ B, int ldb,
                                          const float* __restrict__ bias,
                                          float* __restrict__ C,
                                          int kchunk, int kbeg, int m0, int n0)
{
    extern __shared__ float2 dyn2[];
    float2 (*A2)[20] = (float2(*)[20])dyn2;              // [256][20]: 2 buffers x 128
    float2 (*B2)[20] = (float2(*)[20])(dyn2 + 256 * 20); // [256][20]

    const int tid = threadIdx.x;
    const int lane = tid & 31, wid = tid >> 5;
    const int qr = lane >> 2, qc = lane & 3;
    const int wm = wid >> 2;          // 0..1
    const int wn = wid & 3;           // 0..3
    const int lr = tid >> 1;          // 0..127
    const int lc = (tid & 1) * 8;     // 0 or 8

    const float* Aptr = A + (size_t)(m0 + lr) * lda + kbeg + lc;
    const float* Bptr = B + (size_t)(n0 + lr) * ldb + kbeg + lc;

    float acc[4][4][4] = {};
    float av[8], bv[8];

    // preload + store tile 0 into buffer 0
    *(float4*)&av[0] = *(const float4*)(Aptr);
    *(float4*)&av[4] = *(const float4*)(Aptr + 4);
    *(float4*)&bv[0] = *(const float4*)(Bptr);
    *(float4*)&bv[4] = *(const float4*)(Bptr + 4);
    split_store8(&A2[lr][lc], &B2[lr][lc], av, bv);
    __syncthreads();

    const int niter = kchunk >> 4;
    for (int it = 0; it < niter; it++) {
        const int cur = (it & 1) << 7;
        if (it + 1 < niter) {
            const float* Ap = Aptr + (it + 1) * 16;
            const float* Bp = Bptr + (it + 1) * 16;
            *(float4*)&av[0] = *(const float4*)(Ap);
            *(float4*)&av[4] = *(const float4*)(Ap + 4);
            *(float4*)&bv[0] = *(const float4*)(Bp);
            *(float4*)&bv[4] = *(const float4*)(Bp + 4);
        }

        #pragma unroll
        for (int ks = 0; ks < 2; ks++) {
            const int kk = ks * 8 + qc;
            uint32_t ah[4][4], al[4][4], bh[4][2], bl[4][2];
            #pragma unroll
            for (int mt = 0; mt < 4; mt++) {
                const int mrow = cur + wm * 64 + mt * 16 + qr;
                float2 v0 = A2[mrow][kk];
                float2 v1 = A2[mrow + 8][kk];
                float2 v2 = A2[mrow][kk + 4];
                float2 v3 = A2[mrow + 8][kk + 4];
                ah[mt][0] = fau(v0.x); al[mt][0] = fau(v0.y);
                ah[mt][1] = fau(v1.x); al[mt][1] = fau(v1.y);
                ah[mt][2] = fau(v2.x); al[mt][2] = fau(v2.y);
                ah[mt][3] = fau(v3.x); al[mt][3] = fau(v3.y);
            }
            #pragma unroll
            for (int nt = 0; nt < 4; nt++) {
                const int ncol = cur + wn * 32 + nt * 8 + qr;
                float2 w0 = B2[ncol][kk];
                float2 w1 = B2[ncol][kk + 4];
                bh[nt][0] = fau(w0.x); bl[nt][0] = fau(w0.y);
                bh[nt][1] = fau(w1.x); bl[nt][1] = fau(w1.y);
            }
            #pragma unroll
            for (int mt = 0; mt < 4; mt++)
                #pragma unroll
                for (int nt = 0; nt < 4; nt++)
                    mma_x3(acc[mt][nt], ah[mt], al[mt], bh[nt], bl[nt]);
        }

        if (it + 1 < niter) {
            const int nxt = ((it + 1) & 1) << 7;
            split_store8(&A2[nxt + lr][lc], &B2[nxt + lr][lc], av, bv);
        }
        __syncthreads();
    }

    const int r0 = m0 + wm * 64 + qr;
    const int c0 = n0 + wn * 32 + qc * 2;
    #pragma unroll
    for (int nt = 0; nt < 4; nt++) {
        const int col = c0 + nt * 8;
        float2 bb = bias ? *(const float2*)(bias + col) : make_float2(0.f, 0.f);
        #pragma unroll
        for (int mt = 0; mt < 4; mt++) {
            const int row = r0 + mt * 16;
            *(float2*)(C + (size_t)row * DMODEL + col) =
                make_float2(acc[mt][nt][0] + bb.x, acc[mt][nt][1] + bb.y);
            *(float2*)(C + (size_t)(row + 8) * DMODEL + col) =
                make_float2(acc[mt][nt][2] + bb.x, acc[mt][nt][3] + bb.y);
        }
    }
}

// batched Q/K/V projection: blockIdx.z selects input/weight/bias/output
__global__ void __launch_bounds__(256, 2)
gemm_qkv(const float* q, const float* k, const float* v,
         const float* Wq, const float* Wk, const float* Wv,
         const float* bq, const float* bk, const float* bv,
         float* Cq, float* Ck, float* Cv)
{
    const int z = blockIdx.z;
    const float* A = (z == 0) ? q : (z == 1) ? k : v;
    const float* W = (z == 0) ? Wq : (z == 1) ? Wk : Wv;
    const float* bb = (z == 0) ? bq : (z == 1) ? bk : bv;
    float* C = (z == 0) ? Cq : (z == 1) ? Ck : Cv;
    gemm_core(A, DMODEL, W, DMODEL, bb, C, 256, 0,
              blockIdx.y * 128, blockIdx.x * 128);
}

// generic split-K GEMM (adjV slices, out-proj slices)
__global__ void __launch_bounds__(256, 2)
gemm_mma2(const float* __restrict__ A, int lda, const float* __restrict__ B, int ldb,
          const float* __restrict__ bias, float* __restrict__ C,
          int kchunk, int part_stride)
{
    gemm_core(A, lda, B, ldb, bias, C + (size_t)blockIdx.z * part_stride,
              kchunk, blockIdx.z * kchunk, blockIdx.y * 128, blockIdx.x * 128);
}

// ================= transpose V -> Vt =================
__global__ void transpose_v(const float* __restrict__ src, float* __restrict__ dst)
{
    __shared__ float t[32][33];
    const int x0 = blockIdx.x * 32;
    const int y0 = blockIdx.y * 32;
    #pragma unroll
    for (int j = 0; j < 32; j += 8)
        t[threadIdx.y + j][threadIdx.x] =
            src[(size_t)(x0 + threadIdx.y + j) * DMODEL + y0 + threadIdx.x];
    __syncthreads();
    #pragma unroll
    for (int j = 0; j < 32; j += 8)
        dst[(size_t)(y0 + threadIdx.y + j) * NTOK + x0 + threadIdx.x] =
            t[threadIdx.x][threadIdx.y + j];
}

// ================= split-K reduce (4 parts) + bias, for out-proj =================
__global__ void reduce4_bias(const float* __restrict__ part, const float* __restrict__ bias,
                             float* __restrict__ out)
{
    const int i = blockIdx.x * 256 + threadIdx.x;   // float4 index
    const int Q = NTOK * DMODEL / 4;
    const float4* p = (const float4*)part;
    float4 a = p[i], b = p[i + Q], c = p[i + 2 * Q], d = p[i + 3 * Q];
    float4 bb = *(const float4*)(bias + ((i * 4) & 255));
    float4 r;
    r.x = (a.x + b.x) + (c.x + d.x) + bb.x;
    r.y = (a.y + b.y) + (c.y + d.y) + bb.y;
    r.z = (a.z + b.z) + (c.z + d.z) + bb.z;
    r.w = (a.w + b.w) + (c.w + d.w) + bb.w;
    ((float4*)out)[i] = r;
}

// ================= adjacency row sums =================
__global__ void rowsum_kernel(const float* __restrict__ adj, float* __restrict__ out)
{
    const int row = blockIdx.x;
    const float4* p = (const float4*)(adj + (size_t)row * NTOK);
    float s = 0.f;
    for (int i = threadIdx.x; i < NTOK / 4; i += 256) {
        float4 v = p[i];
        s += (v.x + v.y) + (v.z + v.w);
    }
    #pragma unroll
    for (int o = 16; o; o >>= 1) s += __shfl_xor_sync(0xffffffffu, s, o);
    __shared__ float red[8];
    if ((threadIdx.x & 31) == 0) red[threadIdx.x >> 5] = s;
    __syncthreads();
    if (threadIdx.x < 8) {
        s = red[threadIdx.x];
        #pragma unroll
        for (int o = 4; o; o >>= 1) s += __shfl_xor_sync(0xffu, s, o);
        if (threadIdx.x == 0) out[row] = s;
    }
}

// ================= flash attention (QK x1, PV x3, no-max softmax) =================
// 64 q x 64 k tiles, 8 warps (2m x 2n). Dyn smem 71936 B -> 3 CTAs/SM.
#define QS(r, c)  Qs[(r) * 36 + (c)]
#define KS(r, c)  Ks[(r) * 36 + (c)]
#define VS(r, c)  Vs[(r) * 36 + (c)]
#define PS(r, c)  Ps2[(r) * 68 + (c)]

__global__ void __launch_bounds__(256, 3)
flash_mma2(const float* __restrict__ Q, const float* __restrict__ K,
           const float* __restrict__ V, const float* __restrict__ mask,
           const float* __restrict__ part, const float* __restrict__ rowsum,
           const float* __restrict__ lambdas, float* __restrict__ X)
{
    extern __shared__ float smf[];
    float*  Qs  = smf;                        // [64][36] fp32 (tf32-rounded)
    float*  Ks  = Qs + 2304;                  // [64][36] fp32 (tf32-rounded)
    float2* Vs  = (float2*)(Ks + 2304);       // [64][36] (hi,lo)
    float2* Ps2 = Vs + 2304;                  // [64][68] (hi,lo)
    float*  l_sh = (float*)(Ps2 + 4352);      // [64]

    const int h  = blockIdx.y;
    const int q0 = blockIdx.x * 64;
    const int tid = threadIdx.x;
    const int lane = tid & 31, wid = tid >> 5;
    const int qr = lane >> 2, qc = lane & 3;
    const int wmq = wid >> 1, wnq = wid & 1;
    const int r1 = wmq * 16 + qr;
    const float scale = 0.17677669529663687f;   // 1/sqrt(32)

    #pragma unroll
    for (int it = 0; it < 2; it++) {
        int i = tid + it * 256;
        int r = i >> 3, c = (i & 7) * 4;
        float4 v = *(const float4*)(Q + (size_t)(q0 + r) * DMODEL + h * DK + c);
        *(float4*)&QS(r, c) = make_float4(tf32_rna(v.x), tf32_rna(v.y),
                                          tf32_rna(v.z), tf32_rna(v.w));
    }
    if (tid < 64) l_sh[tid] = 0.f;

    float oacc[2][4] = {};

    for (int kt = 0; kt < NTOK / 64; kt++) {
        const int k0 = kt * 64;
        __syncthreads();
        #pragma unroll
        for (int it = 0; it < 2; it++) {
            int i = tid + it * 256;
            int r = i >> 3, c = (i & 7) * 4;
            float4 kv = *(const float4*)(K + (size_t)(k0 + r) * DMODEL + h * DK + c);
            *(float4*)&KS(r, c) = make_float4(tf32_rna(kv.x), tf32_rna(kv.y),
                                              tf32_rna(kv.z), tf32_rna(kv.w));
            float4 vv = *(const float4*)(V + (size_t)(k0 + r) * DMODEL + h * DK + c);
            float h0 = tf32_rna(vv.x), h1 = tf32_rna(vv.y);
            float h2 = tf32_rna(vv.z), h3 = tf32_rna(vv.w);
            *(float4*)&VS(r, c)     = make_float4(h0, vv.x - h0, h1, vv.y - h1);
            *(float4*)&VS(r, c + 2) = make_float4(h2, vv.z - h2, h3, vv.w - h3);
        }
        __syncthreads();

        // ---- QK^T (single tf32): warp tile 16x32 ----
        float sacc[4][4] = {};
        #pragma unroll
        for (int ks = 0; ks < 4; ks++) {
            const int kk = ks * 8 + qc;
            uint32_t a[4] = { fau(QS(r1, kk)), fau(QS(r1 + 8, kk)),
                              fau(QS(r1, kk + 4)), fau(QS(r1 + 8, kk + 4)) };
            #pragma unroll
            for (int nt = 0; nt < 4; nt++) {
                const int nrow = wnq * 32 + nt * 8 + qr;
                uint32_t b[2] = { fau(KS(nrow, kk)), fau(KS(nrow, kk + 4)) };
                mma_tf32(sacc[nt], a, b);
            }
        }

        // ---- exp + mask in registers; row sums; write P(hi,lo) ----
        float ps1 = 0.f, ps2 = 0.f;
        #pragma unroll
        for (int nt = 0; nt < 4; nt++) {
            const int colb = wnq * 32 + nt * 8 + qc * 2;
            const float* mp = mask + (size_t)(q0 + r1) * NTOK + k0 + colb;
            float2 m1 = *(const float2*)mp;
            float2 m2 = *(const float2*)(mp + 8 * NTOK);
            float p0 = __expf(fmaf(sacc[nt][0], scale, m1.x));
            float p1 = __expf(fmaf(sacc[nt][1], scale, m1.y));
            float p2 = __expf(fmaf(sacc[nt][2], scale, m2.x));
            float p3 = __expf(fmaf(sacc[nt][3], scale, m2.y));
            ps1 += p0 + p1;
            ps2 += p2 + p3;
            float h0 = tf32_rna(p0), h1 = tf32_rna(p1);
            float h2 = tf32_rna(p2), h3 = tf32_rna(p3);
            *(float4*)&PS(r1, colb)     = make_float4(h0, p0 - h0, h1, p1 - h1);
            *(float4*)&PS(r1 + 8, colb) = make_float4(h2, p2 - h2, h3, p3 - h3);
        }
        ps1 += __shfl_xor_sync(0xffffffffu, ps1, 1);
        ps1 += __shfl_xor_sync(0xffffffffu, ps1, 2);
        ps2 += __shfl_xor_sync(0xffffffffu, ps2, 1);
        ps2 += __shfl_xor_sync(0xffffffffu, ps2, 2);
        if (qc == 0) {
            atomicAdd(&l_sh[r1], ps1);
            atomicAdd(&l_sh[r1 + 8], ps2);
        }
        __syncthreads();

        // ---- PV (x3): O[64][32] += P @ V, warp tile 16x16 ----
        #pragma unroll
        for (int ks = 0; ks < 8; ks++) {
            const int kk = ks * 8 + qc;
            float2 p0 = PS(r1, kk);
            float2 p1 = PS(r1 + 8, kk);
            float2 p2 = PS(r1, kk + 4);
            float2 p3 = PS(r1 + 8, kk + 4);
            uint32_t ah[4] = { fau(p0.x), fau(p1.x), fau(p2.x), fau(p3.x) };
            uint32_t al[4] = { fau(p0.y), fau(p1.y), fau(p2.y), fau(p3.y) };
            #pragma unroll
            for (int nt = 0; nt < 2; nt++) {
                const int dcol = wnq * 16 + nt * 8 + qr;
                float2 b0 = VS(kk, dcol);
                float2 b1 = VS(kk + 4, dcol);
                uint32_t bh[2] = { fau(b0.x), fau(b1.x) };
                uint32_t bl[2] = { fau(b0.y), fau(b1.y) };
                mma_x3(oacc[nt], ah, al, bh, bl);
            }
        }
    }
    __syncthreads();

    // ---- epilogue: normalize + lambda blend (sum SPLITK_ADJ adjV partials inline) ----
    const float lam0 = lambdas[0], lam1 = lambdas[1];
    const int row1 = q0 + r1, row2 = row1 + 8;
    const float invl1 = lam0 / l_sh[r1];
    const float invl2 = lam0 / l_sh[r1 + 8];
    const float invd1 = lam1 / (rowsum[row1] + EPSV);
    const float invd2 = lam1 / (rowsum[row2] + EPSV);
    const int NM = NTOK * DMODEL;
    #pragma unroll
    for (int nt = 0; nt < 2; nt++) {
        const int col = h * DK + wnq * 16 + nt * 8 + qc * 2;
        float ax1 = 0.f, ay1 = 0.f, ax2 = 0.f, ay2 = 0.f;
        #pragma unroll
        for (int z = 0; z < SPLITK_ADJ; z++) {
            float2 a1 = *(const float2*)(part + (size_t)z * NM + (size_t)row1 * DMODEL + col);
            float2 a2 = *(const float2*)(part + (size_t)z * NM + (size_t)row2 * DMODEL + col);
            ax1 += a1.x; ay1 += a1.y; ax2 += a2.x; ay2 += a2.y;
        }
        *(float2*)(X + (size_t)row1 * DMODEL + col) =
            make_float2(oacc[nt][0] * invl1 + ax1 * invd1,
                        oacc[nt][1] * invl1 + ay1 * invd1);
        *(float2*)(X + (size_t)row2 * DMODEL + col) =
            make_float2(oacc[nt][2] * invl2 + ax2 * invd2,
                        oacc[nt][3] * invl2 + ay2 * invd2);
    }
}

// ================= launch =================
extern "C" void kernel_launch(void* const* d_in, const int* in_sizes, int n_in,
                              void* d_out, int out_size)
{
    const float* query  = (const float*)d_in[0];
    const float* key    = (const float*)d_in[1];
    const float* value  = (const float*)d_in[2];
    const float* mask   = (const float*)d_in[3];
    const float* adj    = (const float*)d_in[4];
    const float* lambdas= (const float*)d_in[5];
    const float* Wq     = (const float*)d_in[6];
    const float* bq     = (const float*)d_in[7];
    const float* Wk     = (const float*)d_in[8];
    const float* bk     = (const float*)d_in[9];
    const float* Wv     = (const float*)d_in[10];
    const float* bv     = (const float*)d_in[11];
    const float* Wo     = (const float*)d_in[12];
    const float* bo     = (const float*)d_in[13];
    float* out = (float*)d_out;

    void *pQ, *pK, *pV, *pVt, *pX, *pRS, *pPart;
    cudaGetSymbolAddress(&pQ, g_Q);
    cudaGetSymbolAddress(&pK, g_K);
    cudaGetSymbolAddress(&pV, g_V);
    cudaGetSymbolAddress(&pVt, g_Vt);
    cudaGetSymbolAddress(&pX, g_X);
    cudaGetSymbolAddress(&pRS, g_rowsum);
    cudaGetSymbolAddress(&pPart, g_part);

    const int gemm_smem = 81920;
    const int flash_smem = 71936;
    cudaFuncSetAttribute(gemm_qkv, cudaFuncAttributeMaxDynamicSharedMemorySize, gemm_smem);
    cudaFuncSetAttribute(gemm_mma2, cudaFuncAttributeMaxDynamicSharedMemorySize, gemm_smem);
    cudaFuncSetAttribute(flash_mma2, cudaFuncAttributeMaxDynamicSharedMemorySize, flash_smem);

    // batched Q/K/V projections: 144 CTAs
    dim3 gQKV(2, NTOK / 128, 3);
    gemm_qkv<<<gQKV, 256, gemm_smem>>>(query, key, value, Wq, Wk, Wv, bq, bk, bv,
                                       (float*)pQ, (float*)pK, (float*)pV);

    rowsum_kernel<<<NTOK, 256>>>(adj, (float*)pRS);

    // adj @ V: transpose, split-K=6 GEMM (288 CTAs, one 2/SM wave); partials summed in flash
    transpose_v<<<dim3(NTOK / 32, DMODEL / 32), dim3(32, 8)>>>((const float*)pV, (float*)pVt);
    dim3 gAV(2, NTOK / 128, SPLITK_ADJ);
    gemm_mma2<<<gAV, 256, gemm_smem>>>(adj, NTOK, (const float*)pVt, NTOK, nullptr,
                                       (float*)pPart, NTOK / SPLITK_ADJ, NTOK * DMODEL);

    dim3 gFlash(NTOK / 64, NHEAD);
    flash_mma2<<<gFlash, 256, flash_smem>>>((const float*)pQ, (const float*)pK, (const float*)pV,
                                            mask, (const float*)pPart, (const float*)pRS,
                                            lambdas, (float*)pX);

    // output projection: split-K=4 (192 CTAs) + reduce with bias
    dim3 gO(2, NTOK / 128, 4);
    gemm_mma2<<<gO, 256, gemm_smem>>>((const float*)pX, DMODEL, Wo, DMODEL, nullptr,
                                      (float*)pPart, 64, NTOK * DMODEL);
    reduce4_bias<<<NTOK * DMODEL / 4 / 256, 256>>>((const float*)pPart, bo, out);
}

// round 10
// speedup vs baseline: 2.9835x; 1.3224x over previous
#include <cuda_runtime.h>
#include <math.h>
#include <stdint.h>

#define NTOK 3072
#define DMODEL 256
#define NHEAD 8
#define DK 32
#define EPSV 1e-6f
#define SPLITK_ADJ 6

// ---------------- scratch ----------------
__device__ float g_Q[NTOK * DMODEL];
__device__ float g_K[NTOK * DMODEL];
__device__ float g_V[NTOK * DMODEL];
__device__ float g_Vt[DMODEL * NTOK];                 // V transposed [256][3072]
__device__ float g_X[NTOK * DMODEL];
__device__ float g_rowsum[NTOK];
__device__ float g_part[SPLITK_ADJ * NTOK * DMODEL];  // split-K partials (adjV / out-proj)

// ================= mma helpers =================
__device__ __forceinline__ void mma_tf32(float* c, const uint32_t* a, const uint32_t* b)
{
    asm volatile(
        "mma.sync.aligned.m16n8k8.row.col.f32.tf32.tf32.f32 "
        "{%0,%1,%2,%3}, {%4,%5,%6,%7}, {%8,%9}, {%0,%1,%2,%3};"
        : "+f"(c[0]), "+f"(c[1]), "+f"(c[2]), "+f"(c[3])
        : "r"(a[0]), "r"(a[1]), "r"(a[2]), "r"(a[3]), "r"(b[0]), "r"(b[1]));
}

__device__ __forceinline__ float tf32_rna(float x)
{
    float y;
    asm("cvt.rna.tf32.f32 %0, %1;" : "=f"(y) : "f"(x));
    return y;
}

__device__ __forceinline__ uint32_t fau(float x) { return __float_as_uint(x); }

__device__ __forceinline__ void mma_x3(float* c, const uint32_t* ah, const uint32_t* al,
                                       const uint32_t* bh, const uint32_t* bl)
{
    mma_tf32(c, ah, bl);
    mma_tf32(c, al, bh);
    mma_tf32(c, ah, bh);
}

__device__ __forceinline__ float4 rna4(float4 v)
{
    return make_float4(tf32_rna(v.x), tf32_rna(v.y), tf32_rna(v.z), tf32_rna(v.w));
}

__device__ __forceinline__ void split_store8(float2* dstA, float2* dstB,
                                             const float* av, const float* bv)
{
    #pragma unroll
    for (int j = 0; j < 8; j += 2) {
        float ah0 = tf32_rna(av[j]),     bh0 = tf32_rna(bv[j]);
        float ah1 = tf32_rna(av[j + 1]), bh1 = tf32_rna(bv[j + 1]);
        *(float4*)&dstA[j] = make_float4(ah0, av[j] - ah0, ah1, av[j + 1] - ah1);
        *(float4*)&dstB[j] = make_float4(bh0, bv[j] - bh0, bh1, bv[j + 1] - bh1);
    }
}

// ================= pipelined tf32x3 GEMM core (projections / out-proj) =================
__device__ __forceinline__ void gemm_core(const float* __restrict__ A, int lda,
                                          const float* __restrict__ B, int ldb,
                                          const float* __restrict__ bias,
                                          float* __restrict__ C,
                                          int kchunk, int kbeg, int m0, int n0)
{
    extern __shared__ float2 dyn2[];
    float2 (*A2)[20] = (float2(*)[20])dyn2;              // [256][20]: 2 buffers x 128
    float2 (*B2)[20] = (float2(*)[20])(dyn2 + 256 * 20); // [256][20]

    const int tid = threadIdx.x;
    const int lane = tid & 31, wid = tid >> 5;
    const int qr = lane >> 2, qc = lane & 3;
    const int wm = wid >> 2;
    const int wn = wid & 3;
    const int lr = tid >> 1;
    const int lc = (tid & 1) * 8;

    const float* Aptr = A + (size_t)(m0 + lr) * lda + kbeg + lc;
    const float* Bptr = B + (size_t)(n0 + lr) * ldb + kbeg + lc;

    float acc[4][4][4] = {};
    float av[8], bv[8];

    *(float4*)&av[0] = *(const float4*)(Aptr);
    *(float4*)&av[4] = *(const float4*)(Aptr + 4);
    *(float4*)&bv[0] = *(const float4*)(Bptr);
    *(float4*)&bv[4] = *(const float4*)(Bptr + 4);
    split_store8(&A2[lr][lc], &B2[lr][lc], av, bv);
    __syncthreads();

    const int niter = kchunk >> 4;
    for (int it = 0; it < niter; it++) {
        const int cur = (it & 1) << 7;
        if (it + 1 < niter) {
            const float* Ap = Aptr + (it + 1) * 16;
            const float* Bp = Bptr + (it + 1) * 16;
            *(float4*)&av[0] = *(const float4*)(Ap);
            *(float4*)&av[4] = *(const float4*)(Ap + 4);
            *(float4*)&bv[0] = *(const float4*)(Bp);
            *(float4*)&bv[4] = *(const float4*)(Bp + 4);
        }

        #pragma unroll
        for (int ks = 0; ks < 2; ks++) {
            const int kk = ks * 8 + qc;
            uint32_t ah[4][4], al[4][4], bh[4][2], bl[4][2];
            #pragma unroll
            for (int mt = 0; mt < 4; mt++) {
                const int mrow = cur + wm * 64 + mt * 16 + qr;
                float2 v0 = A2[mrow][kk];
                float2 v1 = A2[mrow + 8][kk];
                float2 v2 = A2[mrow][kk + 4];
                float2 v3 = A2[mrow + 8][kk + 4];
                ah[mt][0] = fau(v0.x); al[mt][0] = fau(v0.y);
                ah[mt][1] = fau(v1.x); al[mt][1] = fau(v1.y);
                ah[mt][2] = fau(v2.x); al[mt][2] = fau(v2.y);
                ah[mt][3] = fau(v3.x); al[mt][3] = fau(v3.y);
            }
            #pragma unroll
            for (int nt = 0; nt < 4; nt++) {
                const int ncol = cur + wn * 32 + nt * 8 + qr;
                float2 w0 = B2[ncol][kk];
                float2 w1 = B2[ncol][kk + 4];
                bh[nt][0] = fau(w0.x); bl[nt][0] = fau(w0.y);
                bh[nt][1] = fau(w1.x); bl[nt][1] = fau(w1.y);
            }
            #pragma unroll
            for (int mt = 0; mt < 4; mt++)
                #pragma unroll
                for (int nt = 0; nt < 4; nt++)
                    mma_x3(acc[mt][nt], ah[mt], al[mt], bh[nt], bl[nt]);
        }

        if (it + 1 < niter) {
            const int nxt = ((it + 1) & 1) << 7;
            split_store8(&A2[nxt + lr][lc], &B2[nxt + lr][lc], av, bv);
        }
        __syncthreads();
    }

    const int r0 = m0 + wm * 64 + qr;
    const int c0 = n0 + wn * 32 + qc * 2;
    #pragma unroll
    for (int nt = 0; nt < 4; nt++) {
        const int col = c0 + nt * 8;
        float2 bb = bias ? *(const float2*)(bias + col) : make_float2(0.f, 0.f);
        #pragma unroll
        for (int mt = 0; mt < 4; mt++) {
            const int row = r0 + mt * 16;
            *(float2*)(C + (size_t)row * DMODEL + col) =
                make_float2(acc[mt][nt][0] + bb.x, acc[mt][nt][1] + bb.y);
            *(float2*)(C + (size_t)(row + 8) * DMODEL + col) =
                make_float2(acc[mt][nt][2] + bb.x, acc[mt][nt][3] + bb.y);
        }
    }
}

__global__ void __launch_bounds__(256, 2)
gemm_qkv(const float* q, const float* k, const float* v,
         const float* Wq, const float* Wk, const float* Wv,
         const float* bq, const float* bk, const float* bv,
         float* Cq, float* Ck, float* Cv)
{
    const int z = blockIdx.z;
    const float* A = (z == 0) ? q : (z == 1) ? k : v;
    const float* W = (z == 0) ? Wq : (z == 1) ? Wk : Wv;
    const float* bb = (z == 0) ? bq : (z == 1) ? bk : bv;
    float* C = (z == 0) ? Cq : (z == 1) ? Ck : Cv;
    gemm_core(A, DMODEL, W, DMODEL, bb, C, 256, 0,
              blockIdx.y * 128, blockIdx.x * 128);
}

__global__ void __launch_bounds__(256, 2)
gemm_mma2(const float* __restrict__ A, int lda, const float* __restrict__ B, int ldb,
          const float* __restrict__ bias, float* __restrict__ C,
          int kchunk, int part_stride)
{
    gemm_core(A, lda, B, ldb, bias, C + (size_t)blockIdx.z * part_stride,
              kchunk, blockIdx.z * kchunk, blockIdx.y * 128, blockIdx.x * 128);
}

// ================= adjV GEMM, single tf32, pipelined =================
// Cpart[z] = adj[:, chunk] @ Vt[:, chunk]^T. 128x128 tiles, fp32 smem (tf32-rounded).
__global__ void __launch_bounds__(256, 2)
gemm_adjv_x1(const float* __restrict__ A, const float* __restrict__ B,
             float* __restrict__ Cpart)
{
    extern __shared__ float dyn1[];
    float (*A1)[20] = (float(*)[20])dyn1;               // [256][20] (2 buffers)
    float (*B1)[20] = (float(*)[20])(dyn1 + 256 * 20);

    const int tid = threadIdx.x;
    const int lane = tid & 31, wid = tid >> 5;
    const int qr = lane >> 2, qc = lane & 3;
    const int wm = wid >> 2, wn = wid & 3;
    const int n0 = blockIdx.x * 128;
    const int m0 = blockIdx.y * 128;
    const int kbeg = blockIdx.z * (NTOK / SPLITK_ADJ);
    const int lr = tid >> 1, lc = (tid & 1) * 8;

    const float* Aptr = A + (size_t)(m0 + lr) * NTOK + kbeg + lc;
    const float* Bptr = B + (size_t)(n0 + lr) * NTOK + kbeg + lc;

    float acc[4][4][4] = {};
    float4 a0, a1, b0, b1;

    a0 = *(const float4*)(Aptr);
    a1 = *(const float4*)(Aptr + 4);
    b0 = *(const float4*)(Bptr);
    b1 = *(const float4*)(Bptr + 4);
    *(float4*)&A1[lr][lc] = rna4(a0);
    *(float4*)&A1[lr][lc + 4] = rna4(a1);
    *(float4*)&B1[lr][lc] = rna4(b0);
    *(float4*)&B1[lr][lc + 4] = rna4(b1);
    __syncthreads();

    const int niter = (NTOK / SPLITK_ADJ) >> 4;
    for (int it = 0; it < niter; it++) {
        const int cur = (it & 1) << 7;
        if (it + 1 < niter) {
            const float* Ap = Aptr + (it + 1) * 16;
            const float* Bp = Bptr + (it + 1) * 16;
            a0 = *(const float4*)(Ap);
            a1 = *(const float4*)(Ap + 4);
            b0 = *(const float4*)(Bp);
            b1 = *(const float4*)(Bp + 4);
        }

        #pragma unroll
        for (int ks = 0; ks < 2; ks++) {
            const int kk = ks * 8 + qc;
            uint32_t a[4][4], b[4][2];
            #pragma unroll
            for (int mt = 0; mt < 4; mt++) {
                const int mrow = cur + wm * 64 + mt * 16 + qr;
                a[mt][0] = fau(A1[mrow][kk]);
                a[mt][1] = fau(A1[mrow + 8][kk]);
                a[mt][2] = fau(A1[mrow][kk + 4]);
                a[mt][3] = fau(A1[mrow + 8][kk + 4]);
            }
            #pragma unroll
            for (int nt = 0; nt < 4; nt++) {
                const int ncol = cur + wn * 32 + nt * 8 + qr;
                b[nt][0] = fau(B1[ncol][kk]);
                b[nt][1] = fau(B1[ncol][kk + 4]);
            }
            #pragma unroll
            for (int mt = 0; mt < 4; mt++)
                #pragma unroll
                for (int nt = 0; nt < 4; nt++)
                    mma_tf32(acc[mt][nt], a[mt], b[nt]);
        }

        if (it + 1 < niter) {
            const int nxt = ((it + 1) & 1) << 7;
            *(float4*)&A1[nxt + lr][lc] = rna4(a0);
            *(float4*)&A1[nxt + lr][lc + 4] = rna4(a1);
            *(float4*)&B1[nxt + lr][lc] = rna4(b0);
            *(float4*)&B1[nxt + lr][lc + 4] = rna4(b1);
        }
        __syncthreads();
    }

    float* Cp = Cpart + (size_t)blockIdx.z * (NTOK * DMODEL);
    const int r0 = m0 + wm * 64 + qr;
    const int c0 = n0 + wn * 32 + qc * 2;
    #pragma unroll
    for (int nt = 0; nt < 4; nt++) {
        const int col = c0 + nt * 8;
        #pragma unroll
        for (int mt = 0; mt < 4; mt++) {
            const int row = r0 + mt * 16;
            *(float2*)(Cp + (size_t)row * DMODEL + col) =
                make_float2(acc[mt][nt][0], acc[mt][nt][1]);
            *(float2*)(Cp + (size_t)(row + 8) * DMODEL + col) =
                make_float2(acc[mt][nt][2], acc[mt][nt][3]);
        }
    }
}

// ================= transpose V -> Vt =================
__global__ void transpose_v(const float* __restrict__ src, float* __restrict__ dst)
{
    __shared__ float t[32][33];
    const int x0 = blockIdx.x * 32;
    const int y0 = blockIdx.y * 32;
    #pragma unroll
    for (int j = 0; j < 32; j += 8)
        t[threadIdx.y + j][threadIdx.x] =
            src[(size_t)(x0 + threadIdx.y + j) * DMODEL + y0 + threadIdx.x];
    __syncthreads();
    #pragma unroll
    for (int j = 0; j < 32; j += 8)
        dst[(size_t)(y0 + threadIdx.y + j) * NTOK + x0 + threadIdx.x] =
            t[threadIdx.x][threadIdx.y + j];
}

// ================= split-K reduce (4 parts) + bias, out-proj =================
__global__ void reduce4_bias(const float* __restrict__ part, const float* __restrict__ bias,
                             float* __restrict__ out)
{
    const int i = blockIdx.x * 256 + threadIdx.x;
    const int Q = NTOK * DMODEL / 4;
    const float4* p = (const float4*)part;
    float4 a = p[i], b = p[i + Q], c = p[i + 2 * Q], d = p[i + 3 * Q];
    float4 bb = *(const float4*)(bias + ((i * 4) & 255));
    float4 r;
    r.x = (a.x + b.x) + (c.x + d.x) + bb.x;
    r.y = (a.y + b.y) + (c.y + d.y) + bb.y;
    r.z = (a.z + b.z) + (c.z + d.z) + bb.z;
    r.w = (a.w + b.w) + (c.w + d.w) + bb.w;
    ((float4*)out)[i] = r;
}

// ================= adjacency row sums =================
__global__ void rowsum_kernel(const float* __restrict__ adj, float* __restrict__ out)
{
    const int row = blockIdx.x;
    const float4* p = (const float4*)(adj + (size_t)row * NTOK);
    float s = 0.f;
    for (int i = threadIdx.x; i < NTOK / 4; i += 256) {
        float4 v = p[i];
        s += (v.x + v.y) + (v.z + v.w);
    }
    #pragma unroll
    for (int o = 16; o; o >>= 1) s += __shfl_xor_sync(0xffffffffu, s, o);
    __shared__ float red[8];
    if ((threadIdx.x & 31) == 0) red[threadIdx.x >> 5] = s;
    __syncthreads();
    if (threadIdx.x < 8) {
        s = red[threadIdx.x];
        #pragma unroll
        for (int o = 4; o; o >>= 1) s += __shfl_xor_sync(0xffu, s, o);
        if (threadIdx.x == 0) out[row] = s;
    }
}

// ================= flash attention (QK x1, PV x2, prefetch-pipelined) =================
// 64 q x 64 k tiles, 8 warps (2m x 2n). Dyn smem 63744 B -> 3 CTAs/SM.
#define QS(r, c)  Qs[(r) * 36 + (c)]
#define KS(r, c)  Ks[(r) * 36 + (c)]
#define VS(r, c)  Vs[(r) * 40 + (c)]
#define PS(r, c)  Ps2[(r) * 68 + (c)]

__global__ void __launch_bounds__(256, 3)
flash_mma3(const float* __restrict__ Q, const float* __restrict__ K,
           const float* __restrict__ V, const float* __restrict__ mask,
           const float* __restrict__ part, const float* __restrict__ rowsum,
           const float* __restrict__ lambdas, float* __restrict__ X)
{
    extern __shared__ float smf[];
    float*  Qs  = smf;                        // [64][36] tf32-rounded
    float*  Ks  = Qs + 64 * 36;               // [64][36] tf32-rounded
    float*  Vs  = Ks + 64 * 36;               // [64][40] tf32-rounded
    float2* Ps2 = (float2*)(Vs + 64 * 40);    // [64][68] (hi,lo)
    float*  l_sh = (float*)(Ps2 + 64 * 68);   // [64]

    const int h  = blockIdx.y;
    const int q0 = blockIdx.x * 64;
    const int tid = threadIdx.x;
    const int lane = tid & 31, wid = tid >> 5;
    const int qr = lane >> 2, qc = lane & 3;
    const int wmq = wid >> 1, wnq = wid & 1;
    const int r1 = wmq * 16 + qr;
    const float scale = 0.17677669529663687f;   // 1/sqrt(32)

    const int ldr = tid >> 3;                 // 0..31 (+32 on second step)
    const int ldc = (tid & 7) * 4;

    // load Q tile (tf32-rounded)
    #pragma unroll
    for (int it = 0; it < 2; it++) {
        const int r = ldr + it * 32;
        float4 v = *(const float4*)(Q + (size_t)(q0 + r) * DMODEL + h * DK + ldc);
        *(float4*)&QS(r, ldc) = rna4(v);
    }
    if (tid < 64) l_sh[tid] = 0.f;

    // prefetch tile 0 K/V into registers
    float4 pk[2], pv[2];
    #pragma unroll
    for (int it = 0; it < 2; it++) {
        const int r = ldr + it * 32;
        pk[it] = *(const float4*)(K + (size_t)r * DMODEL + h * DK + ldc);
        pv[it] = *(const float4*)(V + (size_t)r * DMODEL + h * DK + ldc);
    }

    float oacc[2][4] = {};

    for (int kt = 0; kt < NTOK / 64; kt++) {
        const int k0 = kt * 64;
        __syncthreads();   // prev tile compute done with Ks/Vs/Ps2
        // store prefetched K/V
        #pragma unroll
        for (int it = 0; it < 2; it++) {
            const int r = ldr + it * 32;
            *(float4*)&KS(r, ldc) = rna4(pk[it]);
            *(float4*)&VS(r, ldc) = rna4(pv[it]);
        }
        __syncthreads();
        // prefetch next tile
        if (kt + 1 < NTOK / 64) {
            const int kn = k0 + 64;
            #pragma unroll
            for (int it = 0; it < 2; it++) {
                const int r = kn + ldr + it * 32;
                pk[it] = *(const float4*)(K + (size_t)r * DMODEL + h * DK + ldc);
                pv[it] = *(const float4*)(V + (size_t)r * DMODEL + h * DK + ldc);
            }
        }

        // ---- QK^T (single tf32): warp tile 16x32 ----
        float sacc[4][4] = {};
        #pragma unroll
        for (int ks = 0; ks < 4; ks++) {
            const int kk = ks * 8 + qc;
            uint32_t a[4] = { fau(QS(r1, kk)), fau(QS(r1 + 8, kk)),
                              fau(QS(r1, kk + 4)), fau(QS(r1 + 8, kk + 4)) };
            #pragma unroll
            for (int nt = 0; nt < 4; nt++) {
                const int nrow = wnq * 32 + nt * 8 + qr;
                uint32_t b[2] = { fau(KS(nrow, kk)), fau(KS(nrow, kk + 4)) };
                mma_tf32(sacc[nt], a, b);
            }
        }

        // ---- exp + mask; row sums; write P(hi,lo) ----
        float ps1 = 0.f, ps2 = 0.f;
        #pragma unroll
        for (int nt = 0; nt < 4; nt++) {
            const int colb = wnq * 32 + nt * 8 + qc * 2;
            const float* mp = mask + (size_t)(q0 + r1) * NTOK + k0 + colb;
            float2 m1 = *(const float2*)mp;
            float2 m2 = *(const float2*)(mp + 8 * NTOK);
            float p0 = __expf(fmaf(sacc[nt][0], scale, m1.x));
            float p1 = __expf(fmaf(sacc[nt][1], scale, m1.y));
            float p2 = __expf(fmaf(sacc[nt][2], scale, m2.x));
            float p3 = __expf(fmaf(sacc[nt][3], scale, m2.y));
            ps1 += p0 + p1;
            ps2 += p2 + p3;
            float h0 = tf32_rna(p0), h1 = tf32_rna(p1);
            float h2 = tf32_rna(p2), h3 = tf32_rna(p3);
            *(float4*)&PS(r1, colb)     = make_float4(h0, p0 - h0, h1, p1 - h1);
            *(float4*)&PS(r1 + 8, colb) = make_float4(h2, p2 - h2, h3, p3 - h3);
        }
        ps1 += __shfl_xor_sync(0xffffffffu, ps1, 1);
        ps1 += __shfl_xor_sync(0xffffffffu, ps1, 2);
        ps2 += __shfl_xor_sync(0xffffffffu, ps2, 1);
        ps2 += __shfl_xor_sync(0xffffffffu, ps2, 2);
        if (qc == 0) {
            atomicAdd(&l_sh[r1], ps1);
            atomicAdd(&l_sh[r1 + 8], ps2);
        }
        __syncthreads();   // Ps2 complete

        // ---- PV (x2: P split, V rounded): O[64][32] += P @ V ----
        #pragma unroll
        for (int ks = 0; ks < 8; ks++) {
            const int kk = ks * 8 + qc;
            float2 p0 = PS(r1, kk);
            float2 p1 = PS(r1 + 8, kk);
            float2 p2 = PS(r1, kk + 4);
            float2 p3 = PS(r1 + 8, kk + 4);
            uint32_t ah[4] = { fau(p0.x), fau(p1.x), fau(p2.x), fau(p3.x) };
            uint32_t al[4] = { fau(p0.y), fau(p1.y), fau(p2.y), fau(p3.y) };
            #pragma unroll
            for (int nt = 0; nt < 2; nt++) {
                const int dcol = wnq * 16 + nt * 8 + qr;
                uint32_t b[2] = { fau(VS(kk, dcol)), fau(VS(kk + 4, dcol)) };
                mma_tf32(oacc[nt], ah, b);
                mma_tf32(oacc[nt], al, b);
            }
        }
    }
    __syncthreads();   // l_sh complete

    // ---- epilogue: normalize + lambda blend (sum SPLITK_ADJ adjV partials) ----
    const float lam0 = lambdas[0], lam1 = lambdas[1];
    const int row1 = q0 + r1, row2 = row1 + 8;
    const float invl1 = lam0 / l_sh[r1];
    const float invl2 = lam0 / l_sh[r1 + 8];
    const float invd1 = lam1 / (rowsum[row1] + EPSV);
    const float invd2 = lam1 / (rowsum[row2] + EPSV);
    const int NM = NTOK * DMODEL;
    #pragma unroll
    for (int nt = 0; nt < 2; nt++) {
        const int col = h * DK + wnq * 16 + nt * 8 + qc * 2;
        float ax1 = 0.f, ay1 = 0.f, ax2 = 0.f, ay2 = 0.f;
        #pragma unroll
        for (int z = 0; z < SPLITK_ADJ; z++) {
            float2 a1 = *(const float2*)(part + (size_t)z * NM + (size_t)row1 * DMODEL + col);
            float2 a2 = *(const float2*)(part + (size_t)z * NM + (size_t)row2 * DMODEL + col);
            ax1 += a1.x; ay1 += a1.y; ax2 += a2.x; ay2 += a2.y;
        }
        *(float2*)(X + (size_t)row1 * DMODEL + col) =
            make_float2(oacc[nt][0] * invl1 + ax1 * invd1,
                        oacc[nt][1] * invl1 + ay1 * invd1);
        *(float2*)(X + (size_t)row2 * DMODEL + col) =
            make_float2(oacc[nt][2] * invl2 + ax2 * invd2,
                        oacc[nt][3] * invl2 + ay2 * invd2);
    }
}

// ================= launch =================
extern "C" void kernel_launch(void* const* d_in, const int* in_sizes, int n_in,
                              void* d_out, int out_size)
{
    const float* query  = (const float*)d_in[0];
    const float* key    = (const float*)d_in[1];
    const float* value  = (const float*)d_in[2];
    const float* mask   = (const float*)d_in[3];
    const float* adj    = (const float*)d_in[4];
    const float* lambdas= (const float*)d_in[5];
    const float* Wq     = (const float*)d_in[6];
    const float* bq     = (const float*)d_in[7];
    const float* Wk     = (const float*)d_in[8];
    const float* bk     = (const float*)d_in[9];
    const float* Wv     = (const float*)d_in[10];
    const float* bv     = (const float*)d_in[11];
    const float* Wo     = (const float*)d_in[12];
    const float* bo     = (const float*)d_in[13];
    float* out = (float*)d_out;

    void *pQ, *pK, *pV, *pVt, *pX, *pRS, *pPart;
    cudaGetSymbolAddress(&pQ, g_Q);
    cudaGetSymbolAddress(&pK, g_K);
    cudaGetSymbolAddress(&pV, g_V);
    cudaGetSymbolAddress(&pVt, g_Vt);
    cudaGetSymbolAddress(&pX, g_X);
    cudaGetSymbolAddress(&pRS, g_rowsum);
    cudaGetSymbolAddress(&pPart, g_part);

    const int gemm_smem = 81920;
    const int adjv_smem = 40960;
    const int flash_smem = 63744;
    cudaFuncSetAttribute(gemm_qkv, cudaFuncAttributeMaxDynamicSharedMemorySize, gemm_smem);
    cudaFuncSetAttribute(gemm_mma2, cudaFuncAttributeMaxDynamicSharedMemorySize, gemm_smem);
    cudaFuncSetAttribute(gemm_adjv_x1, cudaFuncAttributeMaxDynamicSharedMemorySize, adjv_smem);
    cudaFuncSetAttribute(flash_mma3, cudaFuncAttributeMaxDynamicSharedMemorySize, flash_smem);

    // batched Q/K/V projections: 144 CTAs
    dim3 gQKV(2, NTOK / 128, 3);
    gemm_qkv<<<gQKV, 256, gemm_smem>>>(query, key, value, Wq, Wk, Wv, bq, bk, bv,
                                       (float*)pQ, (float*)pK, (float*)pV);

    rowsum_kernel<<<NTOK, 256>>>(adj, (float*)pRS);

    // adj @ V: transpose, single-tf32 split-K=6 GEMM (288 CTAs); partials summed in flash
    transpose_v<<<dim3(NTOK / 32, DMODEL / 32), dim3(32, 8)>>>((const float*)pV, (float*)pVt);
    dim3 gAV(2, NTOK / 128, SPLITK_ADJ);
    gemm_adjv_x1<<<gAV, 256, adjv_smem>>>(adj, (const float*)pVt, (float*)pPart);

    dim3 gFlash(NTOK / 64, NHEAD);
    flash_mma3<<<gFlash, 256, flash_smem>>>((const float*)pQ, (const float*)pK, (const float*)pV,
                                            mask, (const float*)pPart, (const float*)pRS,
                                            lambdas, (float*)pX);

    // output projection: split-K=4 (192 CTAs) + reduce with bias
    dim3 gO(2, NTOK / 128, 4);
    gemm_mma2<<<gO, 256, gemm_smem>>>((const float*)pX, DMODEL, Wo, DMODEL, nullptr,
                                      (float*)pPart, 64, NTOK * DMODEL);
    reduce4_bias<<<NTOK * DMODEL / 4 / 256, 256>>>((const float*)pPart, bo, out);
}

// round 11
// speedup vs baseline: 3.3038x; 1.1074x over previous
#include <cuda_runtime.h>
#include <math.h>
#include <stdint.h>

#define NTOK 3072
#define DMODEL 256
#define NHEAD 8
#define DK 32
#define EPSV 1e-6f
#define SPLITK_ADJ 6

// ---------------- scratch ----------------
__device__ float g_Q[NTOK * DMODEL];
__device__ float g_K[NTOK * DMODEL];
__device__ float g_V[NTOK * DMODEL];
__device__ float g_Vt[DMODEL * NTOK];                 // V transposed [256][3072]
__device__ float g_X[NTOK * DMODEL];
__device__ float g_rowsum[NTOK];
__device__ float g_part[SPLITK_ADJ * NTOK * DMODEL];  // split-K partials (adjV / out-proj)

// ================= mma helpers =================
__device__ __forceinline__ void mma_tf32(float* c, const uint32_t* a, const uint32_t* b)
{
    asm volatile(
        "mma.sync.aligned.m16n8k8.row.col.f32.tf32.tf32.f32 "
        "{%0,%1,%2,%3}, {%4,%5,%6,%7}, {%8,%9}, {%0,%1,%2,%3};"
        : "+f"(c[0]), "+f"(c[1]), "+f"(c[2]), "+f"(c[3])
        : "r"(a[0]), "r"(a[1]), "r"(a[2]), "r"(a[3]), "r"(b[0]), "r"(b[1]));
}

__device__ __forceinline__ float tf32_rna(float x)
{
    float y;
    asm("cvt.rna.tf32.f32 %0, %1;" : "=f"(y) : "f"(x));
    return y;
}

__device__ __forceinline__ uint32_t fau(float x) { return __float_as_uint(x); }

__device__ __forceinline__ void mma_x3(float* c, const uint32_t* ah, const uint32_t* al,
                                       const uint32_t* bh, const uint32_t* bl)
{
    mma_tf32(c, ah, bl);
    mma_tf32(c, al, bh);
    mma_tf32(c, ah, bh);
}

__device__ __forceinline__ float4 rna4(float4 v)
{
    return make_float4(tf32_rna(v.x), tf32_rna(v.y), tf32_rna(v.z), tf32_rna(v.w));
}

__device__ __forceinline__ void split_store8(float2* dstA, float2* dstB,
                                             const float* av, const float* bv)
{
    #pragma unroll
    for (int j = 0; j < 8; j += 2) {
        float ah0 = tf32_rna(av[j]),     bh0 = tf32_rna(bv[j]);
        float ah1 = tf32_rna(av[j + 1]), bh1 = tf32_rna(bv[j + 1]);
        *(float4*)&dstA[j] = make_float4(ah0, av[j] - ah0, ah1, av[j + 1] - ah1);
        *(float4*)&dstB[j] = make_float4(bh0, bv[j] - bh0, bh1, bv[j + 1] - bh1);
    }
}

// ================= pipelined tf32x3 GEMM core (projections / out-proj) =================
__device__ __forceinline__ void gemm_core(const float* __restrict__ A, int lda,
                                          const float* __restrict__ B, int ldb,
                                          const float* __restrict__ bias,
                                          float* __restrict__ C,
                                          int kchunk, int kbeg, int m0, int n0)
{
    extern __shared__ float2 dyn2[];
    float2 (*A2)[20] = (float2(*)[20])dyn2;              // [256][20]: 2 buffers x 128
    float2 (*B2)[20] = (float2(*)[20])(dyn2 + 256 * 20); // [256][20]

    const int tid = threadIdx.x;
    const int lane = tid & 31, wid = tid >> 5;
    const int qr = lane >> 2, qc = lane & 3;
    const int wm = wid >> 2;
    const int wn = wid & 3;
    const int lr = tid >> 1;
    const int lc = (tid & 1) * 8;

    const float* Aptr = A + (size_t)(m0 + lr) * lda + kbeg + lc;
    const float* Bptr = B + (size_t)(n0 + lr) * ldb + kbeg + lc;

    float acc[4][4][4] = {};
    float av[8], bv[8];

    *(float4*)&av[0] = *(const float4*)(Aptr);
    *(float4*)&av[4] = *(const float4*)(Aptr + 4);
    *(float4*)&bv[0] = *(const float4*)(Bptr);
    *(float4*)&bv[4] = *(const float4*)(Bptr + 4);
    split_store8(&A2[lr][lc], &B2[lr][lc], av, bv);
    __syncthreads();

    const int niter = kchunk >> 4;
    for (int it = 0; it < niter; it++) {
        const int cur = (it & 1) << 7;
        if (it + 1 < niter) {
            const float* Ap = Aptr + (it + 1) * 16;
            const float* Bp = Bptr + (it + 1) * 16;
            *(float4*)&av[0] = *(const float4*)(Ap);
            *(float4*)&av[4] = *(const float4*)(Ap + 4);
            *(float4*)&bv[0] = *(const float4*)(Bp);
            *(float4*)&bv[4] = *(const float4*)(Bp + 4);
        }

        #pragma unroll
        for (int ks = 0; ks < 2; ks++) {
            const int kk = ks * 8 + qc;
            uint32_t ah[4][4], al[4][4], bh[4][2], bl[4][2];
            #pragma unroll
            for (int mt = 0; mt < 4; mt++) {
                const int mrow = cur + wm * 64 + mt * 16 + qr;
                float2 v0 = A2[mrow][kk];
                float2 v1 = A2[mrow + 8][kk];
                float2 v2 = A2[mrow][kk + 4];
                float2 v3 = A2[mrow + 8][kk + 4];
                ah[mt][0] = fau(v0.x); al[mt][0] = fau(v0.y);
                ah[mt][1] = fau(v1.x); al[mt][1] = fau(v1.y);
                ah[mt][2] = fau(v2.x); al[mt][2] = fau(v2.y);
                ah[mt][3] = fau(v3.x); al[mt][3] = fau(v3.y);
            }
            #pragma unroll
            for (int nt = 0; nt < 4; nt++) {
                const int ncol = cur + wn * 32 + nt * 8 + qr;
                float2 w0 = B2[ncol][kk];
                float2 w1 = B2[ncol][kk + 4];
                bh[nt][0] = fau(w0.x); bl[nt][0] = fau(w0.y);
                bh[nt][1] = fau(w1.x); bl[nt][1] = fau(w1.y);
            }
            #pragma unroll
            for (int mt = 0; mt < 4; mt++)
                #pragma unroll
                for (int nt = 0; nt < 4; nt++)
                    mma_x3(acc[mt][nt], ah[mt], al[mt], bh[nt], bl[nt]);
        }

        if (it + 1 < niter) {
            const int nxt = ((it + 1) & 1) << 7;
            split_store8(&A2[nxt + lr][lc], &B2[nxt + lr][lc], av, bv);
        }
        __syncthreads();
    }

    const int r0 = m0 + wm * 64 + qr;
    const int c0 = n0 + wn * 32 + qc * 2;
    #pragma unroll
    for (int nt = 0; nt < 4; nt++) {
        const int col = c0 + nt * 8;
        float2 bb = bias ? *(const float2*)(bias + col) : make_float2(0.f, 0.f);
        #pragma unroll
        for (int mt = 0; mt < 4; mt++) {
            const int row = r0 + mt * 16;
            *(float2*)(C + (size_t)row * DMODEL + col) =
                make_float2(acc[mt][nt][0] + bb.x, acc[mt][nt][1] + bb.y);
            *(float2*)(C + (size_t)(row + 8) * DMODEL + col) =
                make_float2(acc[mt][nt][2] + bb.x, acc[mt][nt][3] + bb.y);
        }
    }
}

__global__ void __launch_bounds__(256, 2)
gemm_qkv(const float* q, const float* k, const float* v,
         const float* Wq, const float* Wk, const float* Wv,
         const float* bq, const float* bk, const float* bv,
         float* Cq, float* Ck, float* Cv)
{
    const int z = blockIdx.z;
    const float* A = (z == 0) ? q : (z == 1) ? k : v;
    const float* W = (z == 0) ? Wq : (z == 1) ? Wk : Wv;
    const float* bb = (z == 0) ? bq : (z == 1) ? bk : bv;
    float* C = (z == 0) ? Cq : (z == 1) ? Ck : Cv;
    gemm_core(A, DMODEL, W, DMODEL, bb, C, 256, 0,
              blockIdx.y * 128, blockIdx.x * 128);
}

__global__ void __launch_bounds__(256, 2)
gemm_mma2(const float* __restrict__ A, int lda, const float* __restrict__ B, int ldb,
          const float* __restrict__ bias, float* __restrict__ C,
          int kchunk, int part_stride)
{
    gemm_core(A, lda, B, ldb, bias, C + (size_t)blockIdx.z * part_stride,
              kchunk, blockIdx.z * kchunk, blockIdx.y * 128, blockIdx.x * 128);
}

// ================= adjV GEMM, single tf32, pipelined =================
__global__ void __launch_bounds__(256, 2)
gemm_adjv_x1(const float* __restrict__ A, const float* __restrict__ B,
             float* __restrict__ Cpart)
{
    extern __shared__ float dyn1[];
    float (*A1)[20] = (float(*)[20])dyn1;               // [256][20] (2 buffers)
    float (*B1)[20] = (float(*)[20])(dyn1 + 256 * 20);

    const int tid = threadIdx.x;
    const int lane = tid & 31, wid = tid >> 5;
    const int qr = lane >> 2, qc = lane & 3;
    const int wm = wid >> 2, wn = wid & 3;
    const int n0 = blockIdx.x * 128;
    const int m0 = blockIdx.y * 128;
    const int kbeg = blockIdx.z * (NTOK / SPLITK_ADJ);
    const int lr = tid >> 1, lc = (tid & 1) * 8;

    const float* Aptr = A + (size_t)(m0 + lr) * NTOK + kbeg + lc;
    const float* Bptr = B + (size_t)(n0 + lr) * NTOK + kbeg + lc;

    float acc[4][4][4] = {};
    float4 a0, a1, b0, b1;

    a0 = *(const float4*)(Aptr);
    a1 = *(const float4*)(Aptr + 4);
    b0 = *(const float4*)(Bptr);
    b1 = *(const float4*)(Bptr + 4);
    *(float4*)&A1[lr][lc] = rna4(a0);
    *(float4*)&A1[lr][lc + 4] = rna4(a1);
    *(float4*)&B1[lr][lc] = rna4(b0);
    *(float4*)&B1[lr][lc + 4] = rna4(b1);
    __syncthreads();

    const int niter = (NTOK / SPLITK_ADJ) >> 4;
    for (int it = 0; it < niter; it++) {
        const int cur = (it & 1) << 7;
        if (it + 1 < niter) {
            const float* Ap = Aptr + (it + 1) * 16;
            const float* Bp = Bptr + (it + 1) * 16;
            a0 = *(const float4*)(Ap);
            a1 = *(const float4*)(Ap + 4);
            b0 = *(const float4*)(Bp);
            b1 = *(const float4*)(Bp + 4);
        }

        #pragma unroll
        for (int ks = 0; ks < 2; ks++) {
            const int kk = ks * 8 + qc;
            uint32_t a[4][4], b[4][2];
            #pragma unroll
            for (int mt = 0; mt < 4; mt++) {
                const int mrow = cur + wm * 64 + mt * 16 + qr;
                a[mt][0] = fau(A1[mrow][kk]);
                a[mt][1] = fau(A1[mrow + 8][kk]);
                a[mt][2] = fau(A1[mrow][kk + 4]);
                a[mt][3] = fau(A1[mrow + 8][kk + 4]);
            }
            #pragma unroll
            for (int nt = 0; nt < 4; nt++) {
                const int ncol = cur + wn * 32 + nt * 8 + qr;
                b[nt][0] = fau(B1[ncol][kk]);
                b[nt][1] = fau(B1[ncol][kk + 4]);
            }
            #pragma unroll
            for (int mt = 0; mt < 4; mt++)
                #pragma unroll
                for (int nt = 0; nt < 4; nt++)
                    mma_tf32(acc[mt][nt], a[mt], b[nt]);
        }

        if (it + 1 < niter) {
            const int nxt = ((it + 1) & 1) << 7;
            *(float4*)&A1[nxt + lr][lc] = rna4(a0);
            *(float4*)&A1[nxt + lr][lc + 4] = rna4(a1);
            *(float4*)&B1[nxt + lr][lc] = rna4(b0);
            *(float4*)&B1[nxt + lr][lc + 4] = rna4(b1);
        }
        __syncthreads();
    }

    float* Cp = Cpart + (size_t)blockIdx.z * (NTOK * DMODEL);
    const int r0 = m0 + wm * 64 + qr;
    const int c0 = n0 + wn * 32 + qc * 2;
    #pragma unroll
    for (int nt = 0; nt < 4; nt++) {
        const int col = c0 + nt * 8;
        #pragma unroll
        for (int mt = 0; mt < 4; mt++) {
            const int row = r0 + mt * 16;
            *(float2*)(Cp + (size_t)row * DMODEL + col) =
                make_float2(acc[mt][nt][0], acc[mt][nt][1]);
            *(float2*)(Cp + (size_t)(row + 8) * DMODEL + col) =
                make_float2(acc[mt][nt][2], acc[mt][nt][3]);
        }
    }
}

// ================= transpose V -> Vt =================
__global__ void transpose_v(const float* __restrict__ src, float* __restrict__ dst)
{
    __shared__ float t[32][33];
    const int x0 = blockIdx.x * 32;
    const int y0 = blockIdx.y * 32;
    #pragma unroll
    for (int j = 0; j < 32; j += 8)
        t[threadIdx.y + j][threadIdx.x] =
            src[(size_t)(x0 + threadIdx.y + j) * DMODEL + y0 + threadIdx.x];
    __syncthreads();
    #pragma unroll
    for (int j = 0; j < 32; j += 8)
        dst[(size_t)(y0 + threadIdx.y + j) * NTOK + x0 + threadIdx.x] =
            t[threadIdx.x][threadIdx.y + j];
}

// ================= split-K reduce (4 parts) + bias, out-proj =================
__global__ void reduce4_bias(const float* __restrict__ part, const float* __restrict__ bias,
                             float* __restrict__ out)
{
    const int i = blockIdx.x * 256 + threadIdx.x;
    const int Q = NTOK * DMODEL / 4;
    const float4* p = (const float4*)part;
    float4 a = p[i], b = p[i + Q], c = p[i + 2 * Q], d = p[i + 3 * Q];
    float4 bb = *(const float4*)(bias + ((i * 4) & 255));
    float4 r;
    r.x = (a.x + b.x) + (c.x + d.x) + bb.x;
    r.y = (a.y + b.y) + (c.y + d.y) + bb.y;
    r.z = (a.z + b.z) + (c.z + d.z) + bb.z;
    r.w = (a.w + b.w) + (c.w + d.w) + bb.w;
    ((float4*)out)[i] = r;
}

// ================= adjacency row sums =================
__global__ void rowsum_kernel(const float* __restrict__ adj, float* __restrict__ out)
{
    const int row = blockIdx.x;
    const float4* p = (const float4*)(adj + (size_t)row * NTOK);
    float s = 0.f;
    for (int i = threadIdx.x; i < NTOK / 4; i += 256) {
        float4 v = p[i];
        s += (v.x + v.y) + (v.z + v.w);
    }
    #pragma unroll
    for (int o = 16; o; o >>= 1) s += __shfl_xor_sync(0xffffffffu, s, o);
    __shared__ float red[8];
    if ((threadIdx.x & 31) == 0) red[threadIdx.x >> 5] = s;
    __syncthreads();
    if (threadIdx.x < 8) {
        s = red[threadIdx.x];
        #pragma unroll
        for (int o = 4; o; o >>= 1) s += __shfl_xor_sync(0xffu, s, o);
        if (threadIdx.x == 0) out[row] = s;
    }
}

// ================= flash attention (QK x1 with Q-in-regs, PV x1, pipelined) =================
// 64 q x 64 k tiles, 8 warps (2m x 2n). Dyn smem 38144 B -> 3 CTAs/SM.
#define KS(r, c)  Ks[(r) * 36 + (c)]
#define VS(r, c)  Vs[(r) * 40 + (c)]
#define PS(r, c)  Ps[(r) * 72 + (c)]

__global__ void __launch_bounds__(256, 3)
flash_mma4(const float* __restrict__ Q, const float* __restrict__ K,
           const float* __restrict__ V, const float* __restrict__ mask,
           const float* __restrict__ part, const float* __restrict__ rowsum,
           const float* __restrict__ lambdas, float* __restrict__ X)
{
    extern __shared__ float smf[];
    float* Ks = smf;                          // [64][36] tf32-rounded
    float* Vs = Ks + 64 * 36;                 // [64][40] tf32-rounded
    float* Ps = Vs + 64 * 40;                 // [64][72] fp32 (tf32-rounded values)
    float* l_sh = Ps + 64 * 72;               // [64]

    const int h  = blockIdx.y;
    const int q0 = blockIdx.x * 64;
    const int tid = threadIdx.x;
    const int lane = tid & 31, wid = tid >> 5;
    const int qr = lane >> 2, qc = lane & 3;
    const int wmq = wid >> 1, wnq = wid & 1;
    const int r1 = wmq * 16 + qr;
    const float scale = 0.17677669529663687f;   // 1/sqrt(32)

    const int ldr = tid >> 3;                 // 0..31 (+32 on second step)
    const int ldc = (tid & 7) * 4;

    // Q fragments resident in registers (loop-invariant across k-tiles)
    uint32_t qa[4][4];
    {
        const float* Qr0 = Q + (size_t)(q0 + r1) * DMODEL + h * DK;
        const float* Qr1 = Q + (size_t)(q0 + r1 + 8) * DMODEL + h * DK;
        #pragma unroll
        for (int ks = 0; ks < 4; ks++) {
            const int kk = ks * 8 + qc;
            qa[ks][0] = fau(tf32_rna(Qr0[kk]));
            qa[ks][1] = fau(tf32_rna(Qr1[kk]));
            qa[ks][2] = fau(tf32_rna(Qr0[kk + 4]));
            qa[ks][3] = fau(tf32_rna(Qr1[kk + 4]));
        }
    }
    if (tid < 64) l_sh[tid] = 0.f;

    // prefetch tile 0 K/V into registers
    float4 pk[2], pv[2];
    #pragma unroll
    for (int it = 0; it < 2; it++) {
        const int r = ldr + it * 32;
        pk[it] = *(const float4*)(K + (size_t)r * DMODEL + h * DK + ldc);
        pv[it] = *(const float4*)(V + (size_t)r * DMODEL + h * DK + ldc);
    }

    float oacc[2][4] = {};

    for (int kt = 0; kt < NTOK / 64; kt++) {
        const int k0 = kt * 64;
        __syncthreads();   // prev tile compute done with Ks/Vs/Ps
        // store prefetched K/V (tf32-rounded)
        #pragma unroll
        for (int it = 0; it < 2; it++) {
            const int r = ldr + it * 32;
            *(float4*)&KS(r, ldc) = rna4(pk[it]);
            *(float4*)&VS(r, ldc) = rna4(pv[it]);
        }
        __syncthreads();
        // prefetch next tile
        if (kt + 1 < NTOK / 64) {
            const int kn = k0 + 64;
            #pragma unroll
            for (int it = 0; it < 2; it++) {
                const int r = kn + ldr + it * 32;
                pk[it] = *(const float4*)(K + (size_t)r * DMODEL + h * DK + ldc);
                pv[it] = *(const float4*)(V + (size_t)r * DMODEL + h * DK + ldc);
            }
        }

        // ---- QK^T (single tf32, Q in regs): warp tile 16x32 ----
        float sacc[4][4] = {};
        #pragma unroll
        for (int ks = 0; ks < 4; ks++) {
            const int kk = ks * 8 + qc;
            #pragma unroll
            for (int nt = 0; nt < 4; nt++) {
                const int nrow = wnq * 32 + nt * 8 + qr;
                uint32_t b[2] = { fau(KS(nrow, kk)), fau(KS(nrow, kk + 4)) };
                mma_tf32(sacc[nt], qa[ks], b);
            }
        }

        // ---- exp + mask; row sums; write P (fp32, tf32-rounded) ----
        float ps1 = 0.f, ps2 = 0.f;
        #pragma unroll
        for (int nt = 0; nt < 4; nt++) {
            const int colb = wnq * 32 + nt * 8 + qc * 2;
            const float* mp = mask + (size_t)(q0 + r1) * NTOK + k0 + colb;
            float2 m1 = *(const float2*)mp;
            float2 m2 = *(const float2*)(mp + 8 * NTOK);
            float p0 = __expf(fmaf(sacc[nt][0], scale, m1.x));
            float p1 = __expf(fmaf(sacc[nt][1], scale, m1.y));
            float p2 = __expf(fmaf(sacc[nt][2], scale, m2.x));
            float p3 = __expf(fmaf(sacc[nt][3], scale, m2.y));
            ps1 += p0 + p1;
            ps2 += p2 + p3;
            *(float2*)&PS(r1, colb)     = make_float2(tf32_rna(p0), tf32_rna(p1));
            *(float2*)&PS(r1 + 8, colb) = make_float2(tf32_rna(p2), tf32_rna(p3));
        }
        ps1 += __shfl_xor_sync(0xffffffffu, ps1, 1);
        ps1 += __shfl_xor_sync(0xffffffffu, ps1, 2);
        ps2 += __shfl_xor_sync(0xffffffffu, ps2, 1);
        ps2 += __shfl_xor_sync(0xffffffffu, ps2, 2);
        if (qc == 0) {
            atomicAdd(&l_sh[r1], ps1);
            atomicAdd(&l_sh[r1 + 8], ps2);
        }
        __syncthreads();   // Ps complete

        // ---- PV (x1): O[64][32] += P @ V, warp tile 16x16 ----
        #pragma unroll
        for (int ks = 0; ks < 8; ks++) {
            const int kk = ks * 8 + qc;
            uint32_t a[4] = { fau(PS(r1, kk)), fau(PS(r1 + 8, kk)),
                              fau(PS(r1, kk + 4)), fau(PS(r1 + 8, kk + 4)) };
            #pragma unroll
            for (int nt = 0; nt < 2; nt++) {
                const int dcol = wnq * 16 + nt * 8 + qr;
                uint32_t b[2] = { fau(VS(kk, dcol)), fau(VS(kk + 4, dcol)) };
                mma_tf32(oacc[nt], a, b);
            }
        }
    }
    __syncthreads();   // l_sh complete

    // ---- epilogue: normalize + lambda blend (sum SPLITK_ADJ adjV partials) ----
    const float lam0 = lambdas[0], lam1 = lambdas[1];
    const int row1 = q0 + r1, row2 = row1 + 8;
    const float invl1 = lam0 / l_sh[r1];
    const float invl2 = lam0 / l_sh[r1 + 8];
    const float invd1 = lam1 / (rowsum[row1] + EPSV);
    const float invd2 = lam1 / (rowsum[row2] + EPSV);
    const int NM = NTOK * DMODEL;
    #pragma unroll
    for (int nt = 0; nt < 2; nt++) {
        const int col = h * DK + wnq * 16 + nt * 8 + qc * 2;
        float ax1 = 0.f, ay1 = 0.f, ax2 = 0.f, ay2 = 0.f;
        #pragma unroll
        for (int z = 0; z < SPLITK_ADJ; z++) {
            float2 a1 = *(const float2*)(part + (size_t)z * NM + (size_t)row1 * DMODEL + col);
            float2 a2 = *(const float2*)(part + (size_t)z * NM + (size_t)row2 * DMODEL + col);
            ax1 += a1.x; ay1 += a1.y; ax2 += a2.x; ay2 += a2.y;
        }
        *(float2*)(X + (size_t)row1 * DMODEL + col) =
            make_float2(oacc[nt][0] * invl1 + ax1 * invd1,
                        oacc[nt][1] * invl1 + ay1 * invd1);
        *(float2*)(X + (size_t)row2 * DMODEL + col) =
            make_float2(oacc[nt][2] * invl2 + ax2 * invd2,
                        oacc[nt][3] * invl2 + ay2 * invd2);
    }
}

// ================= launch =================
extern "C" void kernel_launch(void* const* d_in, const int* in_sizes, int n_in,
                              void* d_out, int out_size)
{
    const float* query  = (const float*)d_in[0];
    const float* key    = (const float*)d_in[1];
    const float* value  = (const float*)d_in[2];
    const float* mask   = (const float*)d_in[3];
    const float* adj    = (const float*)d_in[4];
    const float* lambdas= (const float*)d_in[5];
    const float* Wq     = (const float*)d_in[6];
    const float* bq     = (const float*)d_in[7];
    const float* Wk     = (const float*)d_in[8];
    const float* bk     = (const float*)d_in[9];
    const float* Wv     = (const float*)d_in[10];
    const float* bv     = (const float*)d_in[11];
    const float* Wo     = (const float*)d_in[12];
    const float* bo     = (const float*)d_in[13];
    float* out = (float*)d_out;

    void *pQ, *pK, *pV, *pVt, *pX, *pRS, *pPart;
    cudaGetSymbolAddress(&pQ, g_Q);
    cudaGetSymbolAddress(&pK, g_K);
    cudaGetSymbolAddress(&pV, g_V);
    cudaGetSymbolAddress(&pVt, g_Vt);
    cudaGetSymbolAddress(&pX, g_X);
    cudaGetSymbolAddress(&pRS, g_rowsum);
    cudaGetSymbolAddress(&pPart, g_part);

    const int gemm_smem = 81920;
    const int adjv_smem = 40960;
    const int flash_smem = (64 * 36 + 64 * 40 + 64 * 72 + 64) * 4;   // 38144
    cudaFuncSetAttribute(gemm_qkv, cudaFuncAttributeMaxDynamicSharedMemorySize, gemm_smem);
    cudaFuncSetAttribute(gemm_mma2, cudaFuncAttributeMaxDynamicSharedMemorySize, gemm_smem);
    cudaFuncSetAttribute(gemm_adjv_x1, cudaFuncAttributeMaxDynamicSharedMemorySize, adjv_smem);
    cudaFuncSetAttribute(flash_mma4, cudaFuncAttributeMaxDynamicSharedMemorySize, flash_smem);

    // batched Q/K/V projections: 144 CTAs
    dim3 gQKV(2, NTOK / 128, 3);
    gemm_qkv<<<gQKV, 256, gemm_smem>>>(query, key, value, Wq, Wk, Wv, bq, bk, bv,
                                       (float*)pQ, (float*)pK, (float*)pV);

    rowsum_kernel<<<NTOK, 256>>>(adj, (float*)pRS);

    // adj @ V: transpose, single-tf32 split-K=6 GEMM (288 CTAs); partials summed in flash
    transpose_v<<<dim3(NTOK / 32, DMODEL / 32), dim3(32, 8)>>>((const float*)pV, (float*)pVt);
    dim3 gAV(2, NTOK / 128, SPLITK_ADJ);
    gemm_adjv_x1<<<gAV, 256, adjv_smem>>>(adj, (const float*)pVt, (float*)pPart);

    dim3 gFlash(NTOK / 64, NHEAD);
    flash_mma4<<<gFlash, 256, flash_smem>>>((const float*)pQ, (const float*)pK, (const float*)pV,
                                            mask, (const float*)pPart, (const float*)pRS,
                                            lambdas, (float*)pX);

    // output projection: split-K=4 (192 CTAs) + reduce with bias
    dim3 gO(2, NTOK / 128, 4);
    gemm_mma2<<<gO, 256, gemm_smem>>>((const float*)pX, DMODEL, Wo, DMODEL, nullptr,
                                      (float*)pPart, 64, NTOK * DMODEL);
    reduce4_bias<<<NTOK * DMODEL / 4 / 256, 256>>>((const float*)pPart, bo, out);
}